// round 14
// baseline (speedup 1.0000x reference)
#include <cuda_runtime.h>
#include <cuda_fp16.h>
#include <math.h>
#include <stdint.h>

#define B_  4
#define L_  256
#define D_  2048
#define LE_ 2048
#define DE_ 1024
#define H_  16
#define HD_ 128
#define BH_ (B_ * H_)

// ---------------- scratch (__device__ globals; alloc-free rule) -------------
__device__ __half g_af[B_ * L_ * D_];            // x rounded fp16
__device__ __half g_ef[B_ * LE_ * DE_];          // enc rounded fp16
__device__ __half g_cf[B_ * L_ * D_];            // ctx fp16
__device__ __half g_wq[D_ * D_];                 // weights fp16, NATURAL [K][N]
__device__ __half g_wk[DE_ * D_];
__device__ __half g_wv[DE_ * D_];
__device__ __half g_wo[D_ * D_];

// attention operands (fp16, head-major [B,H,seq,HD])
__device__ __half g_qf[BH_ * L_ * HD_];          // Q fp16 (rope+scale)
__device__ __half g_kf[BH_ * LE_ * HD_];         // K fp16
__device__ __half g_vf[BH_ * LE_ * HD_];         // V fp16

// ---------------- PTX helpers ----------------------------------------------
__device__ __forceinline__ void ldsm4(uint32_t* r, uint32_t addr) {
    asm volatile("ldmatrix.sync.aligned.m8n8.x4.shared.b16 {%0,%1,%2,%3}, [%4];"
                 : "=r"(r[0]), "=r"(r[1]), "=r"(r[2]), "=r"(r[3]) : "r"(addr));
}
__device__ __forceinline__ void ldsm4t(uint32_t* r, uint32_t addr) {
    asm volatile("ldmatrix.sync.aligned.m8n8.x4.trans.shared.b16 {%0,%1,%2,%3}, [%4];"
                 : "=r"(r[0]), "=r"(r[1]), "=r"(r[2]), "=r"(r[3]) : "r"(addr));
}
__device__ __forceinline__ void mma_f16(float* c, const uint32_t* a,
                                        uint32_t b0, uint32_t b1) {
    asm volatile(
        "mma.sync.aligned.m16n8k16.row.col.f32.f16.f16.f32 "
        "{%0,%1,%2,%3}, {%4,%5,%6,%7}, {%8,%9}, {%0,%1,%2,%3};"
        : "+f"(c[0]), "+f"(c[1]), "+f"(c[2]), "+f"(c[3])
        : "r"(a[0]), "r"(a[1]), "r"(a[2]), "r"(a[3]), "r"(b0), "r"(b1));
}
__device__ __forceinline__ void cp16(uint32_t dst, const void* src) {
    asm volatile("cp.async.cg.shared.global [%0], [%1], 16;" :: "r"(dst), "l"(src));
}
#define CP_COMMIT() asm volatile("cp.async.commit_group;")
#define CP_WAIT0()  asm volatile("cp.async.wait_group 0;")
#define CP_WAIT2()  asm volatile("cp.async.wait_group 2;")

__device__ __forceinline__ uint32_t packh(float a, float b) {
    __half2 t = __floats2half2_rn(a, b);
    return *(uint32_t*)&t;
}

// A-tile smem offset: rows of 64B (32 halves), 16B chunks, XOR swizzle.
__device__ __forceinline__ uint32_t sw_off(int row, int ch) {
    return (uint32_t)(row * 64 + ((ch ^ ((row >> 1) & 3)) << 4));
}
// B-tile (256B rows, 16 chunks) swizzle — same as attention K/V tiles.
__device__ __forceinline__ uint32_t sw_off256(int row, int ch) {
    return (uint32_t)(row * 256 + ((ch ^ (row & 7)) << 4));
}

// ---------------- pre-pass: fp32 -> fp16 round (8 elems/thread) -------------
__device__ __forceinline__ void round8(const float4* x, uint4* o, int i) {
    float4 a = x[2 * i], b = x[2 * i + 1];
    uint4 r;
    r.x = packh(a.x, a.y);
    r.y = packh(a.z, a.w);
    r.z = packh(b.x, b.y);
    r.w = packh(b.z, b.w);
    o[i] = r;
}

__global__ __launch_bounds__(256) void roundh_kernel(
    const float4* __restrict__ x, uint4* __restrict__ o)
{
    round8(x, o, blockIdx.x * 256 + threadIdx.x);
}

// all four weight matrices in one launch.
__global__ __launch_bounds__(256) void roundh4_kernel(
    const float4* wq_s, uint4* wq_d, const float4* wk_s, uint4* wk_d,
    const float4* wv_s, uint4* wv_d, const float4* wo_s, uint4* wo_d)
{
    int blk = blockIdx.x;
    if (blk < 2048)       round8(wq_s, wq_d, blk * 256 + threadIdx.x);
    else if (blk < 3072)  round8(wk_s, wk_d, (blk - 2048) * 256 + threadIdx.x);
    else if (blk < 4096)  round8(wv_s, wv_d, (blk - 3072) * 256 + threadIdx.x);
    else                  round8(wo_s, wo_d, (blk - 4096) * 256 + threadIdx.x);
}

// ---------------- fp16 1-product tensor-core GEMM ---------------------------
// C = A*W + bias ; A:[M][K] fp16, W:[K][N] fp16 NATURAL layout (KK compile-time).
// B-fragments via ldmatrix.trans.  Single-sync 4-stage cp.async, unroll 4.
// MODE 0: fp32 C.  MODE 1: rope+scale -> fp16 Oh (head-major, L).
// MODE 2: fp16 -> Oh (head-major, LE).
template<int BM, int KK>
__global__ __launch_bounds__(256, 2) void gemm1_kernel(
    const __half* __restrict__ A, const __half* __restrict__ W,
    const float* __restrict__ bias, float* __restrict__ C,
    __half* __restrict__ Oh, int M, int N, int mode)
{
    const int ABYTES = BM * 64;
    const int STAGE = ABYTES + 8192;
    const int T = KK / 32;

    extern __shared__ uint8_t smraw[];
    uint32_t sbase = (uint32_t)__cvta_generic_to_shared(smraw);

    int tid = threadIdx.x;
    int m0 = blockIdx.y * BM, n0 = blockIdx.x * 128;
    int warp = tid >> 5, lane = tid & 31;
    int wm = warp & 1, wn = warp >> 1;       // 2x4 warps
    int arow = tid >> 2, ach = tid & 3;

    float acc[BM / 32][4][4];
#pragma unroll
    for (int a = 0; a < BM / 32; a++)
#pragma unroll
        for (int b = 0; b < 4; b++)
#pragma unroll
            for (int c = 0; c < 4; c++) acc[a][b][c] = 0.f;

    auto load_stage = [&](int s, int kt) {
        uint32_t st = sbase + s * STAGE;
#pragma unroll
        for (int i = 0; i < BM / 64; i++) {
            int row = arow + 64 * i;
            cp16(st + sw_off(row, ach),
                 A + (size_t)(m0 + row) * KK + kt + ach * 8);
        }
#pragma unroll
        for (int i = 0; i < 2; i++) {
            int id = tid + 256 * i;
            int row = id >> 4, ch = id & 15;
            cp16(st + ABYTES + sw_off256(row, ch),
                 W + (size_t)(kt + row) * N + n0 + ch * 8);
        }
    };

    load_stage(0, 0);
    CP_COMMIT();
    load_stage(1, 32);
    CP_COMMIT();
    load_stage(2, 64);
    CP_COMMIT();

    int r = lane & 7, sub = lane >> 3;
    int b_k_lane = lane & 15;
    int b_ch_lane = lane >> 4;

#pragma unroll 4
    for (int t = 0; t < T; ++t) {
        CP_WAIT2();
        __syncthreads();
        if (t + 3 < T) load_stage((t + 3) & 3, (t + 3) * 32);
        CP_COMMIT();

        uint32_t stb = sbase + (t & 3) * STAGE;
#pragma unroll
        for (int ks = 0; ks < 2; ++ks) {
            uint32_t af[BM / 32][4];
#pragma unroll
            for (int mf = 0; mf < BM / 32; ++mf) {
                int row = wm * (BM / 2) + mf * 16 + (sub & 1) * 8 + r;
                int ch = ks * 2 + (sub >> 1);
                ldsm4(af[mf], stb + sw_off(row, ch));
            }
            uint32_t bw[4][2];
#pragma unroll
            for (int ng = 0; ng < 2; ++ng) {
                int krow = ks * 16 + b_k_lane;
                int ch = wn * 4 + ng * 2 + b_ch_lane;
                uint32_t tmp[4];
                ldsm4t(tmp, stb + ABYTES + sw_off256(krow, ch));
                bw[2 * ng][0] = tmp[0]; bw[2 * ng][1] = tmp[1];
                bw[2 * ng + 1][0] = tmp[2]; bw[2 * ng + 1][1] = tmp[3];
            }
#pragma unroll
            for (int mf = 0; mf < BM / 32; ++mf)
#pragma unroll
                for (int nf = 0; nf < 4; ++nf)
                    mma_f16(acc[mf][nf], af[mf], bw[nf][0], bw[nf][1]);
        }
    }

    int lr = lane >> 2, lc = (lane & 3) * 2;

    if (mode == 0) {
#pragma unroll
        for (int mf = 0; mf < BM / 32; ++mf)
#pragma unroll
            for (int nf = 0; nf < 4; ++nf) {
                int row = m0 + wm * (BM / 2) + mf * 16 + lr;
                int col = n0 + wn * 32 + nf * 8 + lc;
                float b0 = bias[col], b1 = bias[col + 1];
                float2 v0 = make_float2(acc[mf][nf][0] + b0, acc[mf][nf][1] + b1);
                float2 v1 = make_float2(acc[mf][nf][2] + b0, acc[mf][nf][3] + b1);
                *(float2*)&C[(size_t)row * N + col] = v0;
                *(float2*)&C[(size_t)(row + 8) * N + col] = v1;
            }
    } else {
        const float scale = 0.08838834764831845f;  // 1/sqrt(128)
#pragma unroll
        for (int mf = 0; mf < BM / 32; ++mf)
#pragma unroll
            for (int nf = 0; nf < 4; ++nf) {
                int row = m0 + wm * (BM / 2) + mf * 16 + lr;
                int col = n0 + wn * 32 + nf * 8 + lc;
                float b0 = bias[col], b1 = bias[col + 1];
                int hh = col >> 7, d = col & 127;
#pragma unroll
                for (int rr = 0; rr < 2; ++rr) {
                    int r_ = row + rr * 8;
                    float v0 = acc[mf][nf][2 * rr + 0] + b0;
                    float v1 = acc[mf][nf][2 * rr + 1] + b1;
                    if (mode == 1) {
                        int b = r_ >> 8, l = r_ & 255;
                        int j = d >> 1;
                        float e = -((float)(2 * j) / 128.0f) * 9.210340371976184f;
                        float ang = (float)l * expf(e);
                        float sn, cs;
                        sincosf(ang, &sn, &cs);
                        float o1 = (v0 * cs - v1 * sn) * scale;
                        float o2 = (v0 * sn + v1 * cs) * scale;
                        size_t off = ((size_t)(b * H_ + hh) * L_ + l) * HD_ + d;
                        *(uint32_t*)&Oh[off] = packh(o1, o2);
                    } else {
                        int b = r_ >> 11, le = r_ & 2047;
                        size_t off = ((size_t)(b * H_ + hh) * LE_ + le) * HD_ + d;
                        *(uint32_t*)&Oh[off] = packh(v0, v1);
                    }
                }
            }
    }
}

// ---------------- tensor-core flash attention (fp16 x1) ----------------------
// Full-LE per CTA (no split); writes normalized fp16 ctx directly.
// grid (L/128, H, B) = 128 CTAs. occ 1. Single-sync double-buffered mainloop.
__global__ __launch_bounds__(256, 1) void attn_mma_kernel(
    const __half* __restrict__ qf,
    const __half* __restrict__ kf, const __half* __restrict__ vf,
    __half* __restrict__ cf)
{
    extern __shared__ uint8_t smraw[];
    uint32_t sb = (uint32_t)__cvta_generic_to_shared(smraw);

    int b = blockIdx.z, h = blockIdx.y;
    int bh = b * H_ + h;
    int q0 = blockIdx.x * 128;
    int tid = threadIdx.x, warp = tid >> 5, lane = tid & 31;
    int r = lane & 7, sub = lane >> 3;
    int row_lo = lane >> 2, kc = (lane & 3) * 2;
    int qrow = q0 + warp * 16;

    const __half* qb = qf + ((size_t)bh * L_ + qrow) * HD_;
    uint32_t aq[8][4];
#pragma unroll
    for (int kff = 0; kff < 8; kff++) {
        int k0 = kff * 16 + kc;
        aq[kff][0] = *(const uint32_t*)(qb + (size_t)row_lo * HD_ + k0);
        aq[kff][1] = *(const uint32_t*)(qb + (size_t)(row_lo + 8) * HD_ + k0);
        aq[kff][2] = *(const uint32_t*)(qb + (size_t)row_lo * HD_ + k0 + 8);
        aq[kff][3] = *(const uint32_t*)(qb + (size_t)(row_lo + 8) * HD_ + k0 + 8);
    }

    float ctx[16][4];
#pragma unroll
    for (int i = 0; i < 16; i++)
#pragma unroll
        for (int j = 0; j < 4; j++) ctx[i][j] = 0.f;
    float m0 = -1e30f, m1 = -1e30f, l0 = 0.f, l1 = 0.f;

    const __half* khb = kf + (size_t)bh * LE_ * HD_;
    const __half* vhb = vf + (size_t)bh * LE_ * HD_;

#define LOAD_TILE(stage, kt) do {                                              \
        uint32_t st_ = sb + (stage) * 32768;                                   \
        _Pragma("unroll")                                                      \
        for (int i_ = 0; i_ < 4; i_++) {                                       \
            int id_ = tid + 256 * i_;                                          \
            int row_ = id_ >> 4, ch_ = id_ & 15;                               \
            uint32_t off_ = row_ * 256 + (((ch_ ^ (row_ & 7))) << 4);          \
            size_t g_ = (size_t)((kt) + row_) * HD_ + ch_ * 8;                 \
            cp16(st_ + off_, khb + g_);                                        \
            cp16(st_ + 16384 + off_, vhb + g_);                                \
        }                                                                      \
    } while (0)

    LOAD_TILE(0, 0);
    CP_COMMIT();

    int v_le_lane = lane & 15;
    int v_ch_lane = lane >> 4;
    const int NT = LE_ / 64;

    for (int t = 0; t < NT; ++t) {
        CP_WAIT0();
        __syncthreads();
        if (t + 1 < NT) LOAD_TILE((t + 1) & 1, (t + 1) * 64);
        CP_COMMIT();

        uint32_t st = sb + (t & 1) * 32768;

        float S[8][4];
#pragma unroll
        for (int i = 0; i < 8; i++)
#pragma unroll
            for (int j = 0; j < 4; j++) S[i][j] = 0.f;

#pragma unroll
        for (int kff = 0; kff < 8; kff++) {
            uint32_t bk[8][2];
#pragma unroll
            for (int ng = 0; ng < 4; ng++) {
                int krow = ng * 16 + (sub >> 1) * 8 + r;
                int ch = kff * 2 + (sub & 1);
                uint32_t ad = st + krow * 256 + ((ch ^ (krow & 7)) << 4);
                uint32_t tmp[4];
                ldsm4(tmp, ad);
                bk[2 * ng][0] = tmp[0]; bk[2 * ng][1] = tmp[1];
                bk[2 * ng + 1][0] = tmp[2]; bk[2 * ng + 1][1] = tmp[3];
            }
#pragma unroll
            for (int nf = 0; nf < 8; nf++)
                mma_f16(S[nf], aq[kff], bk[nf][0], bk[nf][1]);
        }

        float rmax0 = -1e30f, rmax1 = -1e30f;
#pragma unroll
        for (int nf = 0; nf < 8; nf++) {
            rmax0 = fmaxf(rmax0, fmaxf(S[nf][0], S[nf][1]));
            rmax1 = fmaxf(rmax1, fmaxf(S[nf][2], S[nf][3]));
        }
        rmax0 = fmaxf(rmax0, __shfl_xor_sync(0xffffffffu, rmax0, 1));
        rmax0 = fmaxf(rmax0, __shfl_xor_sync(0xffffffffu, rmax0, 2));
        rmax1 = fmaxf(rmax1, __shfl_xor_sync(0xffffffffu, rmax1, 1));
        rmax1 = fmaxf(rmax1, __shfl_xor_sync(0xffffffffu, rmax1, 2));

        float mn0 = fmaxf(m0, rmax0), mn1 = fmaxf(m1, rmax1);
        float corr0 = __expf(m0 - mn0), corr1 = __expf(m1 - mn1);
        m0 = mn0; m1 = mn1;
        l0 *= corr0; l1 *= corr1;
#pragma unroll
        for (int nf = 0; nf < 16; nf++) {
            ctx[nf][0] *= corr0; ctx[nf][1] *= corr0;
            ctx[nf][2] *= corr1; ctx[nf][3] *= corr1;
        }

        uint32_t ap[4][4];
#pragma unroll
        for (int nf = 0; nf < 8; nf++) {
            float p0 = __expf(S[nf][0] - m0);
            float p1 = __expf(S[nf][1] - m0);
            float p2 = __expf(S[nf][2] - m1);
            float p3 = __expf(S[nf][3] - m1);
            l0 += p0 + p1;
            l1 += p2 + p3;
            int kff = nf >> 1;
            int base = (nf & 1) * 2;
            ap[kff][base + 0] = packh(p0, p1);
            ap[kff][base + 1] = packh(p2, p3);
        }

#pragma unroll
        for (int kff = 0; kff < 4; kff++) {
            int le = kff * 16 + v_le_lane;
#pragma unroll
            for (int dg = 0; dg < 8; dg++) {
                int ch = dg * 2 + v_ch_lane;
                uint32_t ad = st + 16384 + le * 256 + ((ch ^ (le & 7)) << 4);
                uint32_t th[4];
                ldsm4t(th, ad);
                mma_f16(ctx[2 * dg],     ap[kff], th[0], th[1]);
                mma_f16(ctx[2 * dg + 1], ap[kff], th[2], th[3]);
            }
        }
    }

    l0 += __shfl_xor_sync(0xffffffffu, l0, 1);
    l0 += __shfl_xor_sync(0xffffffffu, l0, 2);
    l1 += __shfl_xor_sync(0xffffffffu, l1, 1);
    l1 += __shfl_xor_sync(0xffffffffu, l1, 2);
    float inv0 = 1.f / l0, inv1 = 1.f / l1;

    int grow0 = b * L_ + qrow + row_lo;
#pragma unroll
    for (int nf = 0; nf < 16; nf++) {
        int col = h * HD_ + nf * 8 + kc;
        size_t off0 = (size_t)grow0 * D_ + col;
        size_t off1 = (size_t)(grow0 + 8) * D_ + col;
        *(uint32_t*)&cf[off0] = packh(ctx[nf][0] * inv0, ctx[nf][1] * inv0);
        *(uint32_t*)&cf[off1] = packh(ctx[nf][2] * inv1, ctx[nf][3] * inv1);
    }
}

// ---------------------------------------------------------------------------
extern "C" void kernel_launch(void* const* d_in, const int* in_sizes, int n_in,
                              void* d_out, int out_size)
{
    const float* x   = (const float*)d_in[0];
    const float* enc = (const float*)d_in[1];
    const float* Wq  = (const float*)d_in[2];
    const float* bq  = (const float*)d_in[3];
    const float* Wk  = (const float*)d_in[4];
    const float* bk  = (const float*)d_in[5];
    const float* Wv  = (const float*)d_in[6];
    const float* bv  = (const float*)d_in[7];
    const float* Wo  = (const float*)d_in[8];
    const float* bo  = (const float*)d_in[9];
    float* out = (float*)d_out;

    __half *af, *ef, *cf, *wq, *wk, *wv, *wo;
    __half *qfp, *kfp, *vfp;
    cudaGetSymbolAddress((void**)&af, g_af);
    cudaGetSymbolAddress((void**)&ef, g_ef);
    cudaGetSymbolAddress((void**)&cf, g_cf);
    cudaGetSymbolAddress((void**)&wq, g_wq);
    cudaGetSymbolAddress((void**)&wk, g_wk);
    cudaGetSymbolAddress((void**)&wv, g_wv);
    cudaGetSymbolAddress((void**)&wo, g_wo);
    cudaGetSymbolAddress((void**)&qfp, g_qf);
    cudaGetSymbolAddress((void**)&kfp, g_kf);
    cudaGetSymbolAddress((void**)&vfp, g_vf);

    const int SMEM64 = 4 * (64 * 64 + 8192);     // 49152
    cudaFuncSetAttribute((const void*)gemm1_kernel<64, D_>,
                         cudaFuncAttributeMaxDynamicSharedMemorySize, SMEM64);
    cudaFuncSetAttribute((const void*)gemm1_kernel<64, DE_>,
                         cudaFuncAttributeMaxDynamicSharedMemorySize, SMEM64);
    cudaFuncSetAttribute((const void*)attn_mma_kernel,
                         cudaFuncAttributeMaxDynamicSharedMemorySize, 65536);

    const int M1 = B_ * L_;    // 1024
    const int M2 = B_ * LE_;   // 8192

    // ---- all fp32->fp16 conversions up front ----
    roundh_kernel<<<(M1 * D_) / 2048, 256>>>((const float4*)x, (uint4*)af);
    roundh_kernel<<<(M2 * DE_) / 2048, 256>>>((const float4*)enc, (uint4*)ef);
    roundh4_kernel<<<6144, 256>>>(
        (const float4*)Wq, (uint4*)wq, (const float4*)Wk, (uint4*)wk,
        (const float4*)Wv, (uint4*)wv, (const float4*)Wo, (uint4*)wo);

    // ---- Q = rope(x @ Wq + bq) -> qf fp16 (BM=64, K=2048) ----
    gemm1_kernel<64, D_><<<dim3(D_ / 128, M1 / 64), 256, SMEM64>>>(
        af, wq, bq, nullptr, qfp, M1, D_, 1);

    // ---- K = enc @ Wk + bk -> kf fp16 (BM=64, K=1024) ----
    gemm1_kernel<64, DE_><<<dim3(D_ / 128, M2 / 64), 256, SMEM64>>>(
        ef, wk, bk, nullptr, kfp, M2, D_, 2);

    // ---- V = enc @ Wv + bv -> vf fp16 (BM=64, K=1024) ----
    gemm1_kernel<64, DE_><<<dim3(D_ / 128, M2 / 64), 256, SMEM64>>>(
        ef, wv, bv, nullptr, vfp, M2, D_, 2);

    // ---- flash attention -> ctx fp16 (direct, no split) ----
    attn_mma_kernel<<<dim3(L_ / 128, H_, B_), 256, 65536>>>(
        qfp, kfp, vfp, cf);

    // ---- out = ctx @ Wo + bo (BM=64, K=2048) ----
    gemm1_kernel<64, D_><<<dim3(D_ / 128, M1 / 64), 256, SMEM64>>>(
        cf, wo, bo, out, nullptr, M1, D_, 0);
}

// round 15
// speedup vs baseline: 1.0922x; 1.0922x over previous
#include <cuda_runtime.h>
#include <cuda_fp16.h>
#include <math.h>
#include <stdint.h>

#define B_  4
#define L_  256
#define D_  2048
#define LE_ 2048
#define DE_ 1024
#define H_  16
#define HD_ 128
#define BH_ (B_ * H_)
#define NSPLIT 2
#define KEYS_PER_SPLIT (LE_ / NSPLIT)

// ---------------- scratch (__device__ globals; alloc-free rule) -------------
__device__ __half g_af[B_ * L_ * D_];            // x rounded fp16
__device__ __half g_ef[B_ * LE_ * DE_];          // enc rounded fp16
__device__ __half g_cf[B_ * L_ * D_];            // ctx fp16 (merged)
__device__ __half g_wq[D_ * D_];                 // weights fp16, NATURAL [K][N]
__device__ __half g_wk[DE_ * D_];
__device__ __half g_wv[DE_ * D_];
__device__ __half g_wo[D_ * D_];

// attention operands (fp16, head-major [B,H,seq,HD])
__device__ __half g_qf[BH_ * L_ * HD_];          // Q fp16 (rope+scale)
__device__ __half g_kf[BH_ * LE_ * HD_];         // K fp16
__device__ __half g_vf[BH_ * LE_ * HD_];         // V fp16

// split-KV partials
__device__ float g_pctx[NSPLIT * BH_ * L_ * HD_];    // 16 MB
__device__ float g_pml[NSPLIT * BH_ * L_ * 2];

// ---------------- PTX helpers ----------------------------------------------
__device__ __forceinline__ void ldsm4(uint32_t* r, uint32_t addr) {
    asm volatile("ldmatrix.sync.aligned.m8n8.x4.shared.b16 {%0,%1,%2,%3}, [%4];"
                 : "=r"(r[0]), "=r"(r[1]), "=r"(r[2]), "=r"(r[3]) : "r"(addr));
}
__device__ __forceinline__ void ldsm4t(uint32_t* r, uint32_t addr) {
    asm volatile("ldmatrix.sync.aligned.m8n8.x4.trans.shared.b16 {%0,%1,%2,%3}, [%4];"
                 : "=r"(r[0]), "=r"(r[1]), "=r"(r[2]), "=r"(r[3]) : "r"(addr));
}
__device__ __forceinline__ void mma_f16(float* c, const uint32_t* a,
                                        uint32_t b0, uint32_t b1) {
    asm volatile(
        "mma.sync.aligned.m16n8k16.row.col.f32.f16.f16.f32 "
        "{%0,%1,%2,%3}, {%4,%5,%6,%7}, {%8,%9}, {%0,%1,%2,%3};"
        : "+f"(c[0]), "+f"(c[1]), "+f"(c[2]), "+f"(c[3])
        : "r"(a[0]), "r"(a[1]), "r"(a[2]), "r"(a[3]), "r"(b0), "r"(b1));
}
__device__ __forceinline__ void cp16(uint32_t dst, const void* src) {
    asm volatile("cp.async.cg.shared.global [%0], [%1], 16;" :: "r"(dst), "l"(src));
}
#define CP_COMMIT() asm volatile("cp.async.commit_group;")
#define CP_WAIT0()  asm volatile("cp.async.wait_group 0;")
#define CP_WAIT2()  asm volatile("cp.async.wait_group 2;")

__device__ __forceinline__ uint32_t packh(float a, float b) {
    __half2 t = __floats2half2_rn(a, b);
    return *(uint32_t*)&t;
}

// A-tile smem offset: rows of 64B (32 halves), 16B chunks, XOR swizzle.
__device__ __forceinline__ uint32_t sw_off(int row, int ch) {
    return (uint32_t)(row * 64 + ((ch ^ ((row >> 1) & 3)) << 4));
}
// B-tile (256B rows, 16 chunks) swizzle — same as attention K/V tiles.
__device__ __forceinline__ uint32_t sw_off256(int row, int ch) {
    return (uint32_t)(row * 256 + ((ch ^ (row & 7)) << 4));
}

// ---------------- pre-pass: ALL fp32 -> fp16 rounds in ONE launch -----------
__device__ __forceinline__ void round8(const float4* x, uint4* o, int i) {
    float4 a = x[2 * i], b = x[2 * i + 1];
    uint4 r;
    r.x = packh(a.x, a.y);
    r.y = packh(a.z, a.w);
    r.z = packh(b.x, b.y);
    r.w = packh(b.z, b.w);
    o[i] = r;
}

// blocks: x [0,1024) | enc [1024,5120) | Wq [5120,7168) | Wk [7168,8192)
//         Wv [8192,9216) | Wo [9216,11264)
__global__ __launch_bounds__(256) void round_all_kernel(
    const float4* x_s, uint4* x_d, const float4* e_s, uint4* e_d,
    const float4* wq_s, uint4* wq_d, const float4* wk_s, uint4* wk_d,
    const float4* wv_s, uint4* wv_d, const float4* wo_s, uint4* wo_d)
{
    int blk = blockIdx.x;
    if (blk < 1024)       round8(x_s,  x_d,  blk * 256 + threadIdx.x);
    else if (blk < 5120)  round8(e_s,  e_d,  (blk - 1024) * 256 + threadIdx.x);
    else if (blk < 7168)  round8(wq_s, wq_d, (blk - 5120) * 256 + threadIdx.x);
    else if (blk < 8192)  round8(wk_s, wk_d, (blk - 7168) * 256 + threadIdx.x);
    else if (blk < 9216)  round8(wv_s, wv_d, (blk - 8192) * 256 + threadIdx.x);
    else                  round8(wo_s, wo_d, (blk - 9216) * 256 + threadIdx.x);
}

// ---------------- fp16 1-product tensor-core GEMM ---------------------------
// C = A*W + bias ; A:[M][K] fp16, W:[K][N] fp16 NATURAL layout (KK compile-time).
// B-fragments via ldmatrix.trans.  Single-sync 4-stage cp.async, unroll 4.
// MODE 0: fp32 C.  MODE 1: rope+scale -> fp16 Oh (head-major, L).
// MODE 2: fp16 -> Oh (head-major, LE).
template<int BM, int KK>
__global__ __launch_bounds__(256, 2) void gemm1_kernel(
    const __half* __restrict__ A, const __half* __restrict__ W,
    const float* __restrict__ bias, float* __restrict__ C,
    __half* __restrict__ Oh, int M, int N, int mode)
{
    const int ABYTES = BM * 64;
    const int STAGE = ABYTES + 8192;
    const int T = KK / 32;

    extern __shared__ uint8_t smraw[];
    uint32_t sbase = (uint32_t)__cvta_generic_to_shared(smraw);

    int tid = threadIdx.x;
    int m0 = blockIdx.y * BM, n0 = blockIdx.x * 128;
    int warp = tid >> 5, lane = tid & 31;
    int wm = warp & 1, wn = warp >> 1;       // 2x4 warps
    int arow = tid >> 2, ach = tid & 3;

    float acc[BM / 32][4][4];
#pragma unroll
    for (int a = 0; a < BM / 32; a++)
#pragma unroll
        for (int b = 0; b < 4; b++)
#pragma unroll
            for (int c = 0; c < 4; c++) acc[a][b][c] = 0.f;

    auto load_stage = [&](int s, int kt) {
        uint32_t st = sbase + s * STAGE;
#pragma unroll
        for (int i = 0; i < BM / 64; i++) {
            int row = arow + 64 * i;
            cp16(st + sw_off(row, ach),
                 A + (size_t)(m0 + row) * KK + kt + ach * 8);
        }
#pragma unroll
        for (int i = 0; i < 2; i++) {
            int id = tid + 256 * i;
            int row = id >> 4, ch = id & 15;
            cp16(st + ABYTES + sw_off256(row, ch),
                 W + (size_t)(kt + row) * N + n0 + ch * 8);
        }
    };

    load_stage(0, 0);
    CP_COMMIT();
    load_stage(1, 32);
    CP_COMMIT();
    load_stage(2, 64);
    CP_COMMIT();

    int r = lane & 7, sub = lane >> 3;
    int b_k_lane = lane & 15;
    int b_ch_lane = lane >> 4;

#pragma unroll 4
    for (int t = 0; t < T; ++t) {
        CP_WAIT2();
        __syncthreads();
        if (t + 3 < T) load_stage((t + 3) & 3, (t + 3) * 32);
        CP_COMMIT();

        uint32_t stb = sbase + (t & 3) * STAGE;
#pragma unroll
        for (int ks = 0; ks < 2; ++ks) {
            uint32_t af[BM / 32][4];
#pragma unroll
            for (int mf = 0; mf < BM / 32; ++mf) {
                int row = wm * (BM / 2) + mf * 16 + (sub & 1) * 8 + r;
                int ch = ks * 2 + (sub >> 1);
                ldsm4(af[mf], stb + sw_off(row, ch));
            }
            uint32_t bw[4][2];
#pragma unroll
            for (int ng = 0; ng < 2; ++ng) {
                int krow = ks * 16 + b_k_lane;
                int ch = wn * 4 + ng * 2 + b_ch_lane;
                uint32_t tmp[4];
                ldsm4t(tmp, stb + ABYTES + sw_off256(krow, ch));
                bw[2 * ng][0] = tmp[0]; bw[2 * ng][1] = tmp[1];
                bw[2 * ng + 1][0] = tmp[2]; bw[2 * ng + 1][1] = tmp[3];
            }
#pragma unroll
            for (int mf = 0; mf < BM / 32; ++mf)
#pragma unroll
                for (int nf = 0; nf < 4; ++nf)
                    mma_f16(acc[mf][nf], af[mf], bw[nf][0], bw[nf][1]);
        }
    }

    int lr = lane >> 2, lc = (lane & 3) * 2;

    if (mode == 0) {
#pragma unroll
        for (int mf = 0; mf < BM / 32; ++mf)
#pragma unroll
            for (int nf = 0; nf < 4; ++nf) {
                int row = m0 + wm * (BM / 2) + mf * 16 + lr;
                int col = n0 + wn * 32 + nf * 8 + lc;
                float b0 = bias[col], b1 = bias[col + 1];
                float2 v0 = make_float2(acc[mf][nf][0] + b0, acc[mf][nf][1] + b1);
                float2 v1 = make_float2(acc[mf][nf][2] + b0, acc[mf][nf][3] + b1);
                *(float2*)&C[(size_t)row * N + col] = v0;
                *(float2*)&C[(size_t)(row + 8) * N + col] = v1;
            }
    } else {
        const float scale = 0.08838834764831845f;  // 1/sqrt(128)
#pragma unroll
        for (int mf = 0; mf < BM / 32; ++mf)
#pragma unroll
            for (int nf = 0; nf < 4; ++nf) {
                int row = m0 + wm * (BM / 2) + mf * 16 + lr;
                int col = n0 + wn * 32 + nf * 8 + lc;
                float b0 = bias[col], b1 = bias[col + 1];
                int hh = col >> 7, d = col & 127;
#pragma unroll
                for (int rr = 0; rr < 2; ++rr) {
                    int r_ = row + rr * 8;
                    float v0 = acc[mf][nf][2 * rr + 0] + b0;
                    float v1 = acc[mf][nf][2 * rr + 1] + b1;
                    if (mode == 1) {
                        int b = r_ >> 8, l = r_ & 255;
                        int j = d >> 1;
                        float e = -((float)(2 * j) / 128.0f) * 9.210340371976184f;
                        float ang = (float)l * expf(e);
                        float sn, cs;
                        sincosf(ang, &sn, &cs);
                        float o1 = (v0 * cs - v1 * sn) * scale;
                        float o2 = (v0 * sn + v1 * cs) * scale;
                        size_t off = ((size_t)(b * H_ + hh) * L_ + l) * HD_ + d;
                        *(uint32_t*)&Oh[off] = packh(o1, o2);
                    } else {
                        int b = r_ >> 11, le = r_ & 2047;
                        size_t off = ((size_t)(b * H_ + hh) * LE_ + le) * HD_ + d;
                        *(uint32_t*)&Oh[off] = packh(v0, v1);
                    }
                }
            }
    }
}

// ---------------- tensor-core flash attention (fp16 x1, split-KV) ------------
// occupancy 1; single-sync double-buffered mainloop. grid = 256 CTAs.
__global__ __launch_bounds__(256, 1) void attn_mma_kernel(
    const __half* __restrict__ qf,
    const __half* __restrict__ kf, const __half* __restrict__ vf,
    float* __restrict__ pctx, float* __restrict__ pml)
{
    extern __shared__ uint8_t smraw[];
    uint32_t sb = (uint32_t)__cvta_generic_to_shared(smraw);

    int b = blockIdx.z, h = blockIdx.y;
    int bh = b * H_ + h;
    int split = blockIdx.x & (NSPLIT - 1);
    int q0 = (blockIdx.x / NSPLIT) * 128;
    int kt0 = split * KEYS_PER_SPLIT;
    int tid = threadIdx.x, warp = tid >> 5, lane = tid & 31;
    int r = lane & 7, sub = lane >> 3;
    int row_lo = lane >> 2, kc = (lane & 3) * 2;
    int qrow = q0 + warp * 16;

    const __half* qb = qf + ((size_t)bh * L_ + qrow) * HD_;
    uint32_t aq[8][4];
#pragma unroll
    for (int kff = 0; kff < 8; kff++) {
        int k0 = kff * 16 + kc;
        aq[kff][0] = *(const uint32_t*)(qb + (size_t)row_lo * HD_ + k0);
        aq[kff][1] = *(const uint32_t*)(qb + (size_t)(row_lo + 8) * HD_ + k0);
        aq[kff][2] = *(const uint32_t*)(qb + (size_t)row_lo * HD_ + k0 + 8);
        aq[kff][3] = *(const uint32_t*)(qb + (size_t)(row_lo + 8) * HD_ + k0 + 8);
    }

    float ctx[16][4];
#pragma unroll
    for (int i = 0; i < 16; i++)
#pragma unroll
        for (int j = 0; j < 4; j++) ctx[i][j] = 0.f;
    float m0 = -1e30f, m1 = -1e30f, l0 = 0.f, l1 = 0.f;

    const __half* khb = kf + (size_t)bh * LE_ * HD_;
    const __half* vhb = vf + (size_t)bh * LE_ * HD_;

#define LOAD_TILE(stage, kt) do {                                              \
        uint32_t st_ = sb + (stage) * 32768;                                   \
        _Pragma("unroll")                                                      \
        for (int i_ = 0; i_ < 4; i_++) {                                       \
            int id_ = tid + 256 * i_;                                          \
            int row_ = id_ >> 4, ch_ = id_ & 15;                               \
            uint32_t off_ = row_ * 256 + (((ch_ ^ (row_ & 7))) << 4);          \
            size_t g_ = (size_t)((kt) + row_) * HD_ + ch_ * 8;                 \
            cp16(st_ + off_, khb + g_);                                        \
            cp16(st_ + 16384 + off_, vhb + g_);                                \
        }                                                                      \
    } while (0)

    LOAD_TILE(0, kt0);
    CP_COMMIT();

    int v_le_lane = lane & 15;
    int v_ch_lane = lane >> 4;
    const int NT = KEYS_PER_SPLIT / 64;

    for (int t = 0; t < NT; ++t) {
        CP_WAIT0();
        __syncthreads();
        if (t + 1 < NT) LOAD_TILE((t + 1) & 1, kt0 + (t + 1) * 64);
        CP_COMMIT();

        uint32_t st = sb + (t & 1) * 32768;

        float S[8][4];
#pragma unroll
        for (int i = 0; i < 8; i++)
#pragma unroll
            for (int j = 0; j < 4; j++) S[i][j] = 0.f;

#pragma unroll
        for (int kff = 0; kff < 8; kff++) {
            uint32_t bk[8][2];
#pragma unroll
            for (int ng = 0; ng < 4; ng++) {
                int krow = ng * 16 + (sub >> 1) * 8 + r;
                int ch = kff * 2 + (sub & 1);
                uint32_t ad = st + krow * 256 + ((ch ^ (krow & 7)) << 4);
                uint32_t tmp[4];
                ldsm4(tmp, ad);
                bk[2 * ng][0] = tmp[0]; bk[2 * ng][1] = tmp[1];
                bk[2 * ng + 1][0] = tmp[2]; bk[2 * ng + 1][1] = tmp[3];
            }
#pragma unroll
            for (int nf = 0; nf < 8; nf++)
                mma_f16(S[nf], aq[kff], bk[nf][0], bk[nf][1]);
        }

        float rmax0 = -1e30f, rmax1 = -1e30f;
#pragma unroll
        for (int nf = 0; nf < 8; nf++) {
            rmax0 = fmaxf(rmax0, fmaxf(S[nf][0], S[nf][1]));
            rmax1 = fmaxf(rmax1, fmaxf(S[nf][2], S[nf][3]));
        }
        rmax0 = fmaxf(rmax0, __shfl_xor_sync(0xffffffffu, rmax0, 1));
        rmax0 = fmaxf(rmax0, __shfl_xor_sync(0xffffffffu, rmax0, 2));
        rmax1 = fmaxf(rmax1, __shfl_xor_sync(0xffffffffu, rmax1, 1));
        rmax1 = fmaxf(rmax1, __shfl_xor_sync(0xffffffffu, rmax1, 2));

        float mn0 = fmaxf(m0, rmax0), mn1 = fmaxf(m1, rmax1);
        float corr0 = __expf(m0 - mn0), corr1 = __expf(m1 - mn1);
        m0 = mn0; m1 = mn1;
        l0 *= corr0; l1 *= corr1;
#pragma unroll
        for (int nf = 0; nf < 16; nf++) {
            ctx[nf][0] *= corr0; ctx[nf][1] *= corr0;
            ctx[nf][2] *= corr1; ctx[nf][3] *= corr1;
        }

        uint32_t ap[4][4];
#pragma unroll
        for (int nf = 0; nf < 8; nf++) {
            float p0 = __expf(S[nf][0] - m0);
            float p1 = __expf(S[nf][1] - m0);
            float p2 = __expf(S[nf][2] - m1);
            float p3 = __expf(S[nf][3] - m1);
            l0 += p0 + p1;
            l1 += p2 + p3;
            int kff = nf >> 1;
            int base = (nf & 1) * 2;
            ap[kff][base + 0] = packh(p0, p1);
            ap[kff][base + 1] = packh(p2, p3);
        }

#pragma unroll
        for (int kff = 0; kff < 4; kff++) {
            int le = kff * 16 + v_le_lane;
#pragma unroll
            for (int dg = 0; dg < 8; dg++) {
                int ch = dg * 2 + v_ch_lane;
                uint32_t ad = st + 16384 + le * 256 + ((ch ^ (le & 7)) << 4);
                uint32_t th[4];
                ldsm4t(th, ad);
                mma_f16(ctx[2 * dg],     ap[kff], th[0], th[1]);
                mma_f16(ctx[2 * dg + 1], ap[kff], th[2], th[3]);
            }
        }
    }

    l0 += __shfl_xor_sync(0xffffffffu, l0, 1);
    l0 += __shfl_xor_sync(0xffffffffu, l0, 2);
    l1 += __shfl_xor_sync(0xffffffffu, l1, 1);
    l1 += __shfl_xor_sync(0xffffffffu, l1, 2);

    size_t base = ((size_t)(split * BH_ + bh) * L_ + qrow) * HD_;
#pragma unroll
    for (int nf = 0; nf < 16; nf++) {
        int col = nf * 8 + kc;
        *(float2*)&pctx[base + (size_t)row_lo * HD_ + col] =
            make_float2(ctx[nf][0], ctx[nf][1]);
        *(float2*)&pctx[base + (size_t)(row_lo + 8) * HD_ + col] =
            make_float2(ctx[nf][2], ctx[nf][3]);
    }
    if ((lane & 3) == 0) {
        size_t mb = ((size_t)(split * BH_ + bh) * L_ + qrow) * 2;
        pml[mb + (size_t)row_lo * 2 + 0] = m0;
        pml[mb + (size_t)row_lo * 2 + 1] = l0;
        pml[mb + (size_t)(row_lo + 8) * 2 + 0] = m1;
        pml[mb + (size_t)(row_lo + 8) * 2 + 1] = l1;
    }
}

// ---------------- split-KV merge --------------------------------------------
__global__ __launch_bounds__(256) void attn_merge_kernel(
    const float* __restrict__ pctx, const float* __restrict__ pml,
    __half* __restrict__ cf)
{
    int idx = blockIdx.x * 256 + threadIdx.x;  // BH*L*HD/2 total
    int d2 = idx & 63;
    int l = (idx >> 6) & (L_ - 1);
    int bh = idx >> 14;

    size_t ml0 = ((size_t)(0 * BH_ + bh) * L_ + l) * 2;
    size_t ml1 = ((size_t)(1 * BH_ + bh) * L_ + l) * 2;
    float m0 = pml[ml0], s0 = pml[ml0 + 1];
    float m1 = pml[ml1], s1 = pml[ml1 + 1];
    float M = fmaxf(m0, m1);
    float w0 = __expf(m0 - M), w1 = __expf(m1 - M);
    float inv = 1.f / (s0 * w0 + s1 * w1);

    size_t c0 = ((size_t)(0 * BH_ + bh) * L_ + l) * HD_ + 2 * d2;
    size_t c1 = ((size_t)(1 * BH_ + bh) * L_ + l) * HD_ + 2 * d2;
    float2 a = *(const float2*)&pctx[c0];
    float2 b = *(const float2*)&pctx[c1];
    float o0 = (a.x * w0 + b.x * w1) * inv;
    float o1 = (a.y * w0 + b.y * w1) * inv;

    int bb = bh >> 4, hh = bh & 15;
    size_t off = (size_t)(bb * L_ + l) * D_ + hh * HD_ + 2 * d2;
    *(uint32_t*)&cf[off] = packh(o0, o1);
}

// ---------------------------------------------------------------------------
extern "C" void kernel_launch(void* const* d_in, const int* in_sizes, int n_in,
                              void* d_out, int out_size)
{
    const float* x   = (const float*)d_in[0];
    const float* enc = (const float*)d_in[1];
    const float* Wq  = (const float*)d_in[2];
    const float* bq  = (const float*)d_in[3];
    const float* Wk  = (const float*)d_in[4];
    const float* bk  = (const float*)d_in[5];
    const float* Wv  = (const float*)d_in[6];
    const float* bv  = (const float*)d_in[7];
    const float* Wo  = (const float*)d_in[8];
    const float* bo  = (const float*)d_in[9];
    float* out = (float*)d_out;

    __half *af, *ef, *cf, *wq, *wk, *wv, *wo;
    __half *qfp, *kfp, *vfp;
    float *pctx, *pml;
    cudaGetSymbolAddress((void**)&af, g_af);
    cudaGetSymbolAddress((void**)&ef, g_ef);
    cudaGetSymbolAddress((void**)&cf, g_cf);
    cudaGetSymbolAddress((void**)&wq, g_wq);
    cudaGetSymbolAddress((void**)&wk, g_wk);
    cudaGetSymbolAddress((void**)&wv, g_wv);
    cudaGetSymbolAddress((void**)&wo, g_wo);
    cudaGetSymbolAddress((void**)&qfp, g_qf);
    cudaGetSymbolAddress((void**)&kfp, g_kf);
    cudaGetSymbolAddress((void**)&vfp, g_vf);
    cudaGetSymbolAddress((void**)&pctx, g_pctx);
    cudaGetSymbolAddress((void**)&pml, g_pml);

    const int SMEM64  = 4 * (64 * 64 + 8192);     // 49152
    const int SMEM128 = 4 * (128 * 64 + 8192);    // 65536
    cudaFuncSetAttribute((const void*)gemm1_kernel<64, D_>,
                         cudaFuncAttributeMaxDynamicSharedMemorySize, SMEM64);
    cudaFuncSetAttribute((const void*)gemm1_kernel<128, DE_>,
                         cudaFuncAttributeMaxDynamicSharedMemorySize, SMEM128);
    cudaFuncSetAttribute((const void*)attn_mma_kernel,
                         cudaFuncAttributeMaxDynamicSharedMemorySize, 65536);

    const int M1 = B_ * L_;    // 1024
    const int M2 = B_ * LE_;   // 8192

    // ---- all fp32->fp16 conversions in ONE launch ----
    round_all_kernel<<<11264, 256>>>(
        (const float4*)x, (uint4*)af, (const float4*)enc, (uint4*)ef,
        (const float4*)Wq, (uint4*)wq, (const float4*)Wk, (uint4*)wk,
        (const float4*)Wv, (uint4*)wv, (const float4*)Wo, (uint4*)wo);

    // ---- Q = rope(x @ Wq + bq) -> qf fp16 (BM=64, K=2048) ----
    gemm1_kernel<64, D_><<<dim3(D_ / 128, M1 / 64), 256, SMEM64>>>(
        af, wq, bq, nullptr, qfp, M1, D_, 1);

    // ---- K = enc @ Wk + bk -> kf fp16 (BM=128, K=1024) ----
    gemm1_kernel<128, DE_><<<dim3(D_ / 128, M2 / 128), 256, SMEM128>>>(
        ef, wk, bk, nullptr, kfp, M2, D_, 2);

    // ---- V = enc @ Wv + bv -> vf fp16 (BM=128, K=1024) ----
    gemm1_kernel<128, DE_><<<dim3(D_ / 128, M2 / 128), 256, SMEM128>>>(
        ef, wv, bv, nullptr, vfp, M2, D_, 2);

    // ---- flash attention (split-KV x2) -> partials, then merge ----
    attn_mma_kernel<<<dim3((L_ / 128) * NSPLIT, H_, B_), 256, 65536>>>(
        qfp, kfp, vfp, pctx, pml);
    attn_merge_kernel<<<(BH_ * L_ * HD_ / 2) / 256, 256>>>(pctx, pml, cf);

    // ---- out = ctx @ Wo + bo (BM=64, K=2048) ----
    gemm1_kernel<64, D_><<<dim3(D_ / 128, M1 / 64), 256, SMEM64>>>(
        cf, wo, bo, out, nullptr, M1, D_, 0);
}

// round 16
// speedup vs baseline: 1.1121x; 1.0182x over previous
#include <cuda_runtime.h>
#include <cuda_fp16.h>
#include <math.h>
#include <stdint.h>

#define B_  4
#define L_  256
#define D_  2048
#define LE_ 2048
#define DE_ 1024
#define H_  16
#define HD_ 128
#define BH_ (B_ * H_)
#define NSPLIT 2
#define KEYS_PER_SPLIT (LE_ / NSPLIT)

// ---------------- scratch (__device__ globals; alloc-free rule) -------------
__device__ __half g_af[B_ * L_ * D_];            // x rounded fp16
__device__ __half g_ef[B_ * LE_ * DE_];          // enc rounded fp16
__device__ __half g_cf[B_ * L_ * D_];            // ctx fp16 (merged)
__device__ __half g_wq[D_ * D_];                 // weights fp16, NATURAL [K][N]
__device__ __half g_wk[DE_ * D_];
__device__ __half g_wv[DE_ * D_];
__device__ __half g_wo[D_ * D_];

// attention operands (fp16, head-major [B,H,seq,HD])
__device__ __half g_qf[BH_ * L_ * HD_];          // Q fp16 (rope+scale)
__device__ __half g_kf[BH_ * LE_ * HD_];         // K fp16
__device__ __half g_vf[BH_ * LE_ * HD_];         // V fp16

// split-KV partials
__device__ float g_pctx[NSPLIT * BH_ * L_ * HD_];    // 16 MB
__device__ float g_pml[NSPLIT * BH_ * L_ * 2];

// ---------------- PTX helpers ----------------------------------------------
__device__ __forceinline__ void ldsm4(uint32_t* r, uint32_t addr) {
    asm volatile("ldmatrix.sync.aligned.m8n8.x4.shared.b16 {%0,%1,%2,%3}, [%4];"
                 : "=r"(r[0]), "=r"(r[1]), "=r"(r[2]), "=r"(r[3]) : "r"(addr));
}
__device__ __forceinline__ void ldsm4t(uint32_t* r, uint32_t addr) {
    asm volatile("ldmatrix.sync.aligned.m8n8.x4.trans.shared.b16 {%0,%1,%2,%3}, [%4];"
                 : "=r"(r[0]), "=r"(r[1]), "=r"(r[2]), "=r"(r[3]) : "r"(addr));
}
__device__ __forceinline__ void mma_f16(float* c, const uint32_t* a,
                                        uint32_t b0, uint32_t b1) {
    asm volatile(
        "mma.sync.aligned.m16n8k16.row.col.f32.f16.f16.f32 "
        "{%0,%1,%2,%3}, {%4,%5,%6,%7}, {%8,%9}, {%0,%1,%2,%3};"
        : "+f"(c[0]), "+f"(c[1]), "+f"(c[2]), "+f"(c[3])
        : "r"(a[0]), "r"(a[1]), "r"(a[2]), "r"(a[3]), "r"(b0), "r"(b1));
}
__device__ __forceinline__ void cp16(uint32_t dst, const void* src) {
    asm volatile("cp.async.cg.shared.global [%0], [%1], 16;" :: "r"(dst), "l"(src));
}
#define CP_COMMIT() asm volatile("cp.async.commit_group;")
#define CP_WAIT0()  asm volatile("cp.async.wait_group 0;")
#define CP_WAIT2()  asm volatile("cp.async.wait_group 2;")

__device__ __forceinline__ uint32_t packh(float a, float b) {
    __half2 t = __floats2half2_rn(a, b);
    return *(uint32_t*)&t;
}

// A-tile smem offset: rows of 64B (32 halves), 16B chunks, XOR swizzle.
__device__ __forceinline__ uint32_t sw_off(int row, int ch) {
    return (uint32_t)(row * 64 + ((ch ^ ((row >> 1) & 3)) << 4));
}
// B-tile (256B rows, 16 chunks) swizzle — same as attention K/V tiles.
__device__ __forceinline__ uint32_t sw_off256(int row, int ch) {
    return (uint32_t)(row * 256 + ((ch ^ (row & 7)) << 4));
}

// ---------------- pre-pass: ALL fp32 -> fp16 rounds in ONE launch -----------
__device__ __forceinline__ void round8(const float4* x, uint4* o, int i) {
    float4 a = x[2 * i], b = x[2 * i + 1];
    uint4 r;
    r.x = packh(a.x, a.y);
    r.y = packh(a.z, a.w);
    r.z = packh(b.x, b.y);
    r.w = packh(b.z, b.w);
    o[i] = r;
}

__global__ __launch_bounds__(256) void round_all_kernel(
    const float4* x_s, uint4* x_d, const float4* e_s, uint4* e_d,
    const float4* wq_s, uint4* wq_d, const float4* wk_s, uint4* wk_d,
    const float4* wv_s, uint4* wv_d, const float4* wo_s, uint4* wo_d)
{
    int blk = blockIdx.x;
    if (blk < 1024)       round8(x_s,  x_d,  blk * 256 + threadIdx.x);
    else if (blk < 5120)  round8(e_s,  e_d,  (blk - 1024) * 256 + threadIdx.x);
    else if (blk < 7168)  round8(wq_s, wq_d, (blk - 5120) * 256 + threadIdx.x);
    else if (blk < 8192)  round8(wk_s, wk_d, (blk - 7168) * 256 + threadIdx.x);
    else if (blk < 9216)  round8(wv_s, wv_d, (blk - 8192) * 256 + threadIdx.x);
    else                  round8(wo_s, wo_d, (blk - 9216) * 256 + threadIdx.x);
}

// ---------------- fp16 1-product tensor-core GEMM body ----------------------
// C = A*W + bias ; A:[M][K] fp16, W:[K][N] fp16 NATURAL layout (KK compile-time).
// B-fragments via ldmatrix.trans.  Single-sync 4-stage cp.async, unroll 4.
// MODE 0: fp32 C.  MODE 1: rope+scale -> fp16 Oh (head-major, L).
// MODE 2: fp16 -> Oh (head-major, LE).
template<int BM, int KK>
__device__ __forceinline__ void gemm1_body(
    const __half* __restrict__ A, const __half* __restrict__ W,
    const float* __restrict__ bias, float* __restrict__ C,
    __half* __restrict__ Oh, int M, int N, int mode)
{
    const int ABYTES = BM * 64;
    const int STAGE = ABYTES + 8192;
    const int T = KK / 32;

    extern __shared__ uint8_t smraw[];
    uint32_t sbase = (uint32_t)__cvta_generic_to_shared(smraw);

    int tid = threadIdx.x;
    int m0 = blockIdx.y * BM, n0 = blockIdx.x * 128;
    int warp = tid >> 5, lane = tid & 31;
    int wm = warp & 1, wn = warp >> 1;       // 2x4 warps
    int arow = tid >> 2, ach = tid & 3;

    float acc[BM / 32][4][4];
#pragma unroll
    for (int a = 0; a < BM / 32; a++)
#pragma unroll
        for (int b = 0; b < 4; b++)
#pragma unroll
            for (int c = 0; c < 4; c++) acc[a][b][c] = 0.f;

    auto load_stage = [&](int s, int kt) {
        uint32_t st = sbase + s * STAGE;
#pragma unroll
        for (int i = 0; i < BM / 64; i++) {
            int row = arow + 64 * i;
            cp16(st + sw_off(row, ach),
                 A + (size_t)(m0 + row) * KK + kt + ach * 8);
        }
#pragma unroll
        for (int i = 0; i < 2; i++) {
            int id = tid + 256 * i;
            int row = id >> 4, ch = id & 15;
            cp16(st + ABYTES + sw_off256(row, ch),
                 W + (size_t)(kt + row) * N + n0 + ch * 8);
        }
    };

    load_stage(0, 0);
    CP_COMMIT();
    load_stage(1, 32);
    CP_COMMIT();
    load_stage(2, 64);
    CP_COMMIT();

    int r = lane & 7, sub = lane >> 3;
    int b_k_lane = lane & 15;
    int b_ch_lane = lane >> 4;

#pragma unroll 4
    for (int t = 0; t < T; ++t) {
        CP_WAIT2();
        __syncthreads();
        if (t + 3 < T) load_stage((t + 3) & 3, (t + 3) * 32);
        CP_COMMIT();

        uint32_t stb = sbase + (t & 3) * STAGE;
#pragma unroll
        for (int ks = 0; ks < 2; ++ks) {
            uint32_t af[BM / 32][4];
#pragma unroll
            for (int mf = 0; mf < BM / 32; ++mf) {
                int row = wm * (BM / 2) + mf * 16 + (sub & 1) * 8 + r;
                int ch = ks * 2 + (sub >> 1);
                ldsm4(af[mf], stb + sw_off(row, ch));
            }
            uint32_t bw[4][2];
#pragma unroll
            for (int ng = 0; ng < 2; ++ng) {
                int krow = ks * 16 + b_k_lane;
                int ch = wn * 4 + ng * 2 + b_ch_lane;
                uint32_t tmp[4];
                ldsm4t(tmp, stb + ABYTES + sw_off256(krow, ch));
                bw[2 * ng][0] = tmp[0]; bw[2 * ng][1] = tmp[1];
                bw[2 * ng + 1][0] = tmp[2]; bw[2 * ng + 1][1] = tmp[3];
            }
#pragma unroll
            for (int mf = 0; mf < BM / 32; ++mf)
#pragma unroll
                for (int nf = 0; nf < 4; ++nf)
                    mma_f16(acc[mf][nf], af[mf], bw[nf][0], bw[nf][1]);
        }
    }

    int lr = lane >> 2, lc = (lane & 3) * 2;

    if (mode == 0) {
#pragma unroll
        for (int mf = 0; mf < BM / 32; ++mf)
#pragma unroll
            for (int nf = 0; nf < 4; ++nf) {
                int row = m0 + wm * (BM / 2) + mf * 16 + lr;
                int col = n0 + wn * 32 + nf * 8 + lc;
                float b0 = bias[col], b1 = bias[col + 1];
                float2 v0 = make_float2(acc[mf][nf][0] + b0, acc[mf][nf][1] + b1);
                float2 v1 = make_float2(acc[mf][nf][2] + b0, acc[mf][nf][3] + b1);
                *(float2*)&C[(size_t)row * N + col] = v0;
                *(float2*)&C[(size_t)(row + 8) * N + col] = v1;
            }
    } else {
        const float scale = 0.08838834764831845f;  // 1/sqrt(128)
#pragma unroll
        for (int mf = 0; mf < BM / 32; ++mf)
#pragma unroll
            for (int nf = 0; nf < 4; ++nf) {
                int row = m0 + wm * (BM / 2) + mf * 16 + lr;
                int col = n0 + wn * 32 + nf * 8 + lc;
                float b0 = bias[col], b1 = bias[col + 1];
                int hh = col >> 7, d = col & 127;
#pragma unroll
                for (int rr = 0; rr < 2; ++rr) {
                    int r_ = row + rr * 8;
                    float v0 = acc[mf][nf][2 * rr + 0] + b0;
                    float v1 = acc[mf][nf][2 * rr + 1] + b1;
                    if (mode == 1) {
                        int b = r_ >> 8, l = r_ & 255;
                        int j = d >> 1;
                        float e = -((float)(2 * j) / 128.0f) * 9.210340371976184f;
                        float ang = (float)l * expf(e);
                        float sn, cs;
                        sincosf(ang, &sn, &cs);
                        float o1 = (v0 * cs - v1 * sn) * scale;
                        float o2 = (v0 * sn + v1 * cs) * scale;
                        size_t off = ((size_t)(b * H_ + hh) * L_ + l) * HD_ + d;
                        *(uint32_t*)&Oh[off] = packh(o1, o2);
                    } else {
                        int b = r_ >> 11, le = r_ & 2047;
                        size_t off = ((size_t)(b * H_ + hh) * LE_ + le) * HD_ + d;
                        *(uint32_t*)&Oh[off] = packh(v0, v1);
                    }
                }
            }
    }
}

template<int BM, int KK>
__global__ __launch_bounds__(256, 2) void gemm1_kernel(
    const __half* __restrict__ A, const __half* __restrict__ W,
    const float* __restrict__ bias, float* __restrict__ C,
    __half* __restrict__ Oh, int M, int N, int mode)
{
    gemm1_body<BM, KK>(A, W, bias, C, Oh, M, N, mode);
}

// K and V projections in ONE launch: blockIdx.z selects operand set.
__global__ __launch_bounds__(256, 2) void gemm_kv_kernel(
    const __half* __restrict__ A,
    const __half* __restrict__ Wk, const __half* __restrict__ Wv,
    const float* __restrict__ bk, const float* __restrict__ bv,
    __half* __restrict__ Kf, __half* __restrict__ Vf, int M, int N)
{
    const __half* W = blockIdx.z ? Wv : Wk;
    const float* bias = blockIdx.z ? bv : bk;
    __half* Oh = blockIdx.z ? Vf : Kf;
    gemm1_body<128, DE_>(A, W, bias, nullptr, Oh, M, N, 2);
}

// ---------------- tensor-core flash attention (fp16 x1, split-KV) ------------
__global__ __launch_bounds__(256, 1) void attn_mma_kernel(
    const __half* __restrict__ qf,
    const __half* __restrict__ kf, const __half* __restrict__ vf,
    float* __restrict__ pctx, float* __restrict__ pml)
{
    extern __shared__ uint8_t smraw[];
    uint32_t sb = (uint32_t)__cvta_generic_to_shared(smraw);

    int b = blockIdx.z, h = blockIdx.y;
    int bh = b * H_ + h;
    int split = blockIdx.x & (NSPLIT - 1);
    int q0 = (blockIdx.x / NSPLIT) * 128;
    int kt0 = split * KEYS_PER_SPLIT;
    int tid = threadIdx.x, warp = tid >> 5, lane = tid & 31;
    int r = lane & 7, sub = lane >> 3;
    int row_lo = lane >> 2, kc = (lane & 3) * 2;
    int qrow = q0 + warp * 16;

    const __half* qb = qf + ((size_t)bh * L_ + qrow) * HD_;
    uint32_t aq[8][4];
#pragma unroll
    for (int kff = 0; kff < 8; kff++) {
        int k0 = kff * 16 + kc;
        aq[kff][0] = *(const uint32_t*)(qb + (size_t)row_lo * HD_ + k0);
        aq[kff][1] = *(const uint32_t*)(qb + (size_t)(row_lo + 8) * HD_ + k0);
        aq[kff][2] = *(const uint32_t*)(qb + (size_t)row_lo * HD_ + k0 + 8);
        aq[kff][3] = *(const uint32_t*)(qb + (size_t)(row_lo + 8) * HD_ + k0 + 8);
    }

    float ctx[16][4];
#pragma unroll
    for (int i = 0; i < 16; i++)
#pragma unroll
        for (int j = 0; j < 4; j++) ctx[i][j] = 0.f;
    float m0 = -1e30f, m1 = -1e30f, l0 = 0.f, l1 = 0.f;

    const __half* khb = kf + (size_t)bh * LE_ * HD_;
    const __half* vhb = vf + (size_t)bh * LE_ * HD_;

#define LOAD_TILE(stage, kt) do {                                              \
        uint32_t st_ = sb + (stage) * 32768;                                   \
        _Pragma("unroll")                                                      \
        for (int i_ = 0; i_ < 4; i_++) {                                       \
            int id_ = tid + 256 * i_;                                          \
            int row_ = id_ >> 4, ch_ = id_ & 15;                               \
            uint32_t off_ = row_ * 256 + (((ch_ ^ (row_ & 7))) << 4);          \
            size_t g_ = (size_t)((kt) + row_) * HD_ + ch_ * 8;                 \
            cp16(st_ + off_, khb + g_);                                        \
            cp16(st_ + 16384 + off_, vhb + g_);                                \
        }                                                                      \
    } while (0)

    LOAD_TILE(0, kt0);
    CP_COMMIT();

    int v_le_lane = lane & 15;
    int v_ch_lane = lane >> 4;
    const int NT = KEYS_PER_SPLIT / 64;

    for (int t = 0; t < NT; ++t) {
        CP_WAIT0();
        __syncthreads();
        if (t + 1 < NT) LOAD_TILE((t + 1) & 1, kt0 + (t + 1) * 64);
        CP_COMMIT();

        uint32_t st = sb + (t & 1) * 32768;

        float S[8][4];
#pragma unroll
        for (int i = 0; i < 8; i++)
#pragma unroll
            for (int j = 0; j < 4; j++) S[i][j] = 0.f;

#pragma unroll
        for (int kff = 0; kff < 8; kff++) {
            uint32_t bk[8][2];
#pragma unroll
            for (int ng = 0; ng < 4; ng++) {
                int krow = ng * 16 + (sub >> 1) * 8 + r;
                int ch = kff * 2 + (sub & 1);
                uint32_t ad = st + krow * 256 + ((ch ^ (krow & 7)) << 4);
                uint32_t tmp[4];
                ldsm4(tmp, ad);
                bk[2 * ng][0] = tmp[0]; bk[2 * ng][1] = tmp[1];
                bk[2 * ng + 1][0] = tmp[2]; bk[2 * ng + 1][1] = tmp[3];
            }
#pragma unroll
            for (int nf = 0; nf < 8; nf++)
                mma_f16(S[nf], aq[kff], bk[nf][0], bk[nf][1]);
        }

        float rmax0 = -1e30f, rmax1 = -1e30f;
#pragma unroll
        for (int nf = 0; nf < 8; nf++) {
            rmax0 = fmaxf(rmax0, fmaxf(S[nf][0], S[nf][1]));
            rmax1 = fmaxf(rmax1, fmaxf(S[nf][2], S[nf][3]));
        }
        rmax0 = fmaxf(rmax0, __shfl_xor_sync(0xffffffffu, rmax0, 1));
        rmax0 = fmaxf(rmax0, __shfl_xor_sync(0xffffffffu, rmax0, 2));
        rmax1 = fmaxf(rmax1, __shfl_xor_sync(0xffffffffu, rmax1, 1));
        rmax1 = fmaxf(rmax1, __shfl_xor_sync(0xffffffffu, rmax1, 2));

        float mn0 = fmaxf(m0, rmax0), mn1 = fmaxf(m1, rmax1);
        float corr0 = __expf(m0 - mn0), corr1 = __expf(m1 - mn1);
        m0 = mn0; m1 = mn1;
        l0 *= corr0; l1 *= corr1;
#pragma unroll
        for (int nf = 0; nf < 16; nf++) {
            ctx[nf][0] *= corr0; ctx[nf][1] *= corr0;
            ctx[nf][2] *= corr1; ctx[nf][3] *= corr1;
        }

        uint32_t ap[4][4];
#pragma unroll
        for (int nf = 0; nf < 8; nf++) {
            float p0 = __expf(S[nf][0] - m0);
            float p1 = __expf(S[nf][1] - m0);
            float p2 = __expf(S[nf][2] - m1);
            float p3 = __expf(S[nf][3] - m1);
            l0 += p0 + p1;
            l1 += p2 + p3;
            int kff = nf >> 1;
            int base = (nf & 1) * 2;
            ap[kff][base + 0] = packh(p0, p1);
            ap[kff][base + 1] = packh(p2, p3);
        }

#pragma unroll
        for (int kff = 0; kff < 4; kff++) {
            int le = kff * 16 + v_le_lane;
#pragma unroll
            for (int dg = 0; dg < 8; dg++) {
                int ch = dg * 2 + v_ch_lane;
                uint32_t ad = st + 16384 + le * 256 + ((ch ^ (le & 7)) << 4);
                uint32_t th[4];
                ldsm4t(th, ad);
                mma_f16(ctx[2 * dg],     ap[kff], th[0], th[1]);
                mma_f16(ctx[2 * dg + 1], ap[kff], th[2], th[3]);
            }
        }
    }

    l0 += __shfl_xor_sync(0xffffffffu, l0, 1);
    l0 += __shfl_xor_sync(0xffffffffu, l0, 2);
    l1 += __shfl_xor_sync(0xffffffffu, l1, 1);
    l1 += __shfl_xor_sync(0xffffffffu, l1, 2);

    size_t base = ((size_t)(split * BH_ + bh) * L_ + qrow) * HD_;
#pragma unroll
    for (int nf = 0; nf < 16; nf++) {
        int col = nf * 8 + kc;
        *(float2*)&pctx[base + (size_t)row_lo * HD_ + col] =
            make_float2(ctx[nf][0], ctx[nf][1]);
        *(float2*)&pctx[base + (size_t)(row_lo + 8) * HD_ + col] =
            make_float2(ctx[nf][2], ctx[nf][3]);
    }
    if ((lane & 3) == 0) {
        size_t mb = ((size_t)(split * BH_ + bh) * L_ + qrow) * 2;
        pml[mb + (size_t)row_lo * 2 + 0] = m0;
        pml[mb + (size_t)row_lo * 2 + 1] = l0;
        pml[mb + (size_t)(row_lo + 8) * 2 + 0] = m1;
        pml[mb + (size_t)(row_lo + 8) * 2 + 1] = l1;
    }
}

// ---------------- split-KV merge (8 dims/thread) -----------------------------
__global__ __launch_bounds__(256) void attn_merge_kernel(
    const float* __restrict__ pctx, const float* __restrict__ pml,
    __half* __restrict__ cf)
{
    int idx = blockIdx.x * 256 + threadIdx.x;  // BH*L*HD/8 total
    int d8 = idx & 15;                         // 16 groups of 8 dims
    int l = (idx >> 4) & (L_ - 1);
    int bh = idx >> 12;

    size_t ml0 = ((size_t)(0 * BH_ + bh) * L_ + l) * 2;
    size_t ml1 = ((size_t)(1 * BH_ + bh) * L_ + l) * 2;
    float m0 = pml[ml0], s0 = pml[ml0 + 1];
    float m1 = pml[ml1], s1 = pml[ml1 + 1];
    float M = fmaxf(m0, m1);
    float w0 = __expf(m0 - M), w1 = __expf(m1 - M);
    float inv = 1.f / (s0 * w0 + s1 * w1);
    float f0 = w0 * inv, f1 = w1 * inv;

    size_t c0 = ((size_t)(0 * BH_ + bh) * L_ + l) * HD_ + 8 * d8;
    size_t c1 = ((size_t)(1 * BH_ + bh) * L_ + l) * HD_ + 8 * d8;
    float4 a0 = *(const float4*)&pctx[c0];
    float4 a1 = *(const float4*)&pctx[c0 + 4];
    float4 b0 = *(const float4*)&pctx[c1];
    float4 b1 = *(const float4*)&pctx[c1 + 4];

    uint4 o;
    o.x = packh(a0.x * f0 + b0.x * f1, a0.y * f0 + b0.y * f1);
    o.y = packh(a0.z * f0 + b0.z * f1, a0.w * f0 + b0.w * f1);
    o.z = packh(a1.x * f0 + b1.x * f1, a1.y * f0 + b1.y * f1);
    o.w = packh(a1.z * f0 + b1.z * f1, a1.w * f0 + b1.w * f1);

    int bb = bh >> 4, hh = bh & 15;
    size_t off = (size_t)(bb * L_ + l) * D_ + hh * HD_ + 8 * d8;
    *(uint4*)&cf[off] = o;
}

// ---------------------------------------------------------------------------
extern "C" void kernel_launch(void* const* d_in, const int* in_sizes, int n_in,
                              void* d_out, int out_size)
{
    const float* x   = (const float*)d_in[0];
    const float* enc = (const float*)d_in[1];
    const float* Wq  = (const float*)d_in[2];
    const float* bq  = (const float*)d_in[3];
    const float* Wk  = (const float*)d_in[4];
    const float* bk  = (const float*)d_in[5];
    const float* Wv  = (const float*)d_in[6];
    const float* bv  = (const float*)d_in[7];
    const float* Wo  = (const float*)d_in[8];
    const float* bo  = (const float*)d_in[9];
    float* out = (float*)d_out;

    __half *af, *ef, *cf, *wq, *wk, *wv, *wo;
    __half *qfp, *kfp, *vfp;
    float *pctx, *pml;
    cudaGetSymbolAddress((void**)&af, g_af);
    cudaGetSymbolAddress((void**)&ef, g_ef);
    cudaGetSymbolAddress((void**)&cf, g_cf);
    cudaGetSymbolAddress((void**)&wq, g_wq);
    cudaGetSymbolAddress((void**)&wk, g_wk);
    cudaGetSymbolAddress((void**)&wv, g_wv);
    cudaGetSymbolAddress((void**)&wo, g_wo);
    cudaGetSymbolAddress((void**)&qfp, g_qf);
    cudaGetSymbolAddress((void**)&kfp, g_kf);
    cudaGetSymbolAddress((void**)&vfp, g_vf);
    cudaGetSymbolAddress((void**)&pctx, g_pctx);
    cudaGetSymbolAddress((void**)&pml, g_pml);

    const int SMEM64  = 4 * (64 * 64 + 8192);     // 49152
    const int SMEM128 = 4 * (128 * 64 + 8192);    // 65536
    cudaFuncSetAttribute((const void*)gemm1_kernel<64, D_>,
                         cudaFuncAttributeMaxDynamicSharedMemorySize, SMEM64);
    cudaFuncSetAttribute((const void*)gemm_kv_kernel,
                         cudaFuncAttributeMaxDynamicSharedMemorySize, SMEM128);
    cudaFuncSetAttribute((const void*)attn_mma_kernel,
                         cudaFuncAttributeMaxDynamicSharedMemorySize, 65536);

    const int M1 = B_ * L_;    // 1024
    const int M2 = B_ * LE_;   // 8192

    // ---- all fp32->fp16 conversions in ONE launch ----
    round_all_kernel<<<11264, 256>>>(
        (const float4*)x, (uint4*)af, (const float4*)enc, (uint4*)ef,
        (const float4*)Wq, (uint4*)wq, (const float4*)Wk, (uint4*)wk,
        (const float4*)Wv, (uint4*)wv, (const float4*)Wo, (uint4*)wo);

    // ---- Q = rope(x @ Wq + bq) -> qf fp16 (BM=64, K=2048) ----
    gemm1_kernel<64, D_><<<dim3(D_ / 128, M1 / 64), 256, SMEM64>>>(
        af, wq, bq, nullptr, qfp, M1, D_, 1);

    // ---- K and V projections in ONE launch (BM=128, K=1024, z=2) ----
    gemm_kv_kernel<<<dim3(D_ / 128, M2 / 128, 2), 256, SMEM128>>>(
        ef, wk, wv, bk, bv, kfp, vfp, M2, D_);

    // ---- flash attention (split-KV x2) -> partials, then merge ----
    attn_mma_kernel<<<dim3((L_ / 128) * NSPLIT, H_, B_), 256, 65536>>>(
        qfp, kfp, vfp, pctx, pml);
    attn_merge_kernel<<<(BH_ * L_ * HD_ / 8) / 256, 256>>>(pctx, pml, cf);

    // ---- out = ctx @ Wo + bo (BM=64, K=2048) ----
    gemm1_kernel<64, D_><<<dim3(D_ / 128, M1 / 64), 256, SMEM64>>>(
        cf, wo, bo, out, nullptr, M1, D_, 0);
}

// round 17
// speedup vs baseline: 1.1365x; 1.0220x over previous
#include <cuda_runtime.h>
#include <cuda_fp16.h>
#include <math.h>
#include <stdint.h>

#define B_  4
#define L_  256
#define D_  2048
#define LE_ 2048
#define DE_ 1024
#define H_  16
#define HD_ 128
#define BH_ (B_ * H_)
#define NSPLIT 2
#define KEYS_PER_SPLIT (LE_ / NSPLIT)

// ---------------- scratch (__device__ globals; alloc-free rule) -------------
__device__ __half g_af[B_ * L_ * D_];            // x rounded fp16
__device__ __half g_ef[B_ * LE_ * DE_];          // enc rounded fp16
__device__ __half g_cf[B_ * L_ * D_];            // ctx fp16 (merged)
__device__ __half g_wq[D_ * D_];                 // weights fp16, NATURAL [K][N]
__device__ __half g_wk[DE_ * D_];
__device__ __half g_wv[DE_ * D_];
__device__ __half g_wo[D_ * D_];

// attention operands (fp16, head-major [B,H,seq,HD])
__device__ __half g_qf[BH_ * L_ * HD_];          // Q fp16 (rope+scale)
__device__ __half g_kf[BH_ * LE_ * HD_];         // K fp16
__device__ __half g_vf[BH_ * LE_ * HD_];         // V fp16

// split-KV partials
__device__ float g_pctx[NSPLIT * BH_ * L_ * HD_];    // 16 MB
__device__ float g_pml[NSPLIT * BH_ * L_ * 2];

// ---------------- PTX helpers ----------------------------------------------
__device__ __forceinline__ void ldsm4(uint32_t* r, uint32_t addr) {
    asm volatile("ldmatrix.sync.aligned.m8n8.x4.shared.b16 {%0,%1,%2,%3}, [%4];"
                 : "=r"(r[0]), "=r"(r[1]), "=r"(r[2]), "=r"(r[3]) : "r"(addr));
}
__device__ __forceinline__ void ldsm4t(uint32_t* r, uint32_t addr) {
    asm volatile("ldmatrix.sync.aligned.m8n8.x4.trans.shared.b16 {%0,%1,%2,%3}, [%4];"
                 : "=r"(r[0]), "=r"(r[1]), "=r"(r[2]), "=r"(r[3]) : "r"(addr));
}
__device__ __forceinline__ void mma_f16(float* c, const uint32_t* a,
                                        uint32_t b0, uint32_t b1) {
    asm volatile(
        "mma.sync.aligned.m16n8k16.row.col.f32.f16.f16.f32 "
        "{%0,%1,%2,%3}, {%4,%5,%6,%7}, {%8,%9}, {%0,%1,%2,%3};"
        : "+f"(c[0]), "+f"(c[1]), "+f"(c[2]), "+f"(c[3])
        : "r"(a[0]), "r"(a[1]), "r"(a[2]), "r"(a[3]), "r"(b0), "r"(b1));
}
__device__ __forceinline__ void cp16(uint32_t dst, const void* src) {
    asm volatile("cp.async.cg.shared.global [%0], [%1], 16;" :: "r"(dst), "l"(src));
}
#define CP_COMMIT() asm volatile("cp.async.commit_group;")
#define CP_WAIT0()  asm volatile("cp.async.wait_group 0;")
#define CP_WAIT2()  asm volatile("cp.async.wait_group 2;")

__device__ __forceinline__ uint32_t packh(float a, float b) {
    __half2 t = __floats2half2_rn(a, b);
    return *(uint32_t*)&t;
}

// A-tile smem offset: rows of 64B (32 halves), 16B chunks, XOR swizzle.
__device__ __forceinline__ uint32_t sw_off(int row, int ch) {
    return (uint32_t)(row * 64 + ((ch ^ ((row >> 1) & 3)) << 4));
}
// B-tile (256B rows, 16 chunks) swizzle — same as attention K/V tiles.
__device__ __forceinline__ uint32_t sw_off256(int row, int ch) {
    return (uint32_t)(row * 256 + ((ch ^ (row & 7)) << 4));
}

// ---------------- pre-pass: ALL fp32 -> fp16 rounds in ONE launch -----------
__device__ __forceinline__ void round8(const float4* x, uint4* o, int i) {
    float4 a = x[2 * i], b = x[2 * i + 1];
    uint4 r;
    r.x = packh(a.x, a.y);
    r.y = packh(a.z, a.w);
    r.z = packh(b.x, b.y);
    r.w = packh(b.z, b.w);
    o[i] = r;
}

__global__ __launch_bounds__(256) void round_all_kernel(
    const float4* x_s, uint4* x_d, const float4* e_s, uint4* e_d,
    const float4* wq_s, uint4* wq_d, const float4* wk_s, uint4* wk_d,
    const float4* wv_s, uint4* wv_d, const float4* wo_s, uint4* wo_d)
{
    int blk = blockIdx.x;
    if (blk < 1024)       round8(x_s,  x_d,  blk * 256 + threadIdx.x);
    else if (blk < 5120)  round8(e_s,  e_d,  (blk - 1024) * 256 + threadIdx.x);
    else if (blk < 7168)  round8(wq_s, wq_d, (blk - 5120) * 256 + threadIdx.x);
    else if (blk < 8192)  round8(wk_s, wk_d, (blk - 7168) * 256 + threadIdx.x);
    else if (blk < 9216)  round8(wv_s, wv_d, (blk - 8192) * 256 + threadIdx.x);
    else                  round8(wo_s, wo_d, (blk - 9216) * 256 + threadIdx.x);
}

// ---------------- fp16 1-product tensor-core GEMM body ----------------------
// C = A*W + bias ; A:[M][K] fp16, W:[K][N] fp16 NATURAL layout (KK compile-time).
// B-fragments via ldmatrix.trans.  Single-sync 4-stage cp.async, unroll 4.
// MODE 0: fp32 C.  MODE 1: rope+scale -> fp16 Oh (head-major, L).
// MODE 2: fp16 -> Oh (head-major, LE).
template<int BM, int KK>
__device__ __forceinline__ void gemm1_body(
    const __half* __restrict__ A, const __half* __restrict__ W,
    const float* __restrict__ bias, float* __restrict__ C,
    __half* __restrict__ Oh, int M, int N, int mode, int m0, int n0)
{
    const int ABYTES = BM * 64;
    const int STAGE = ABYTES + 8192;
    const int T = KK / 32;

    extern __shared__ uint8_t smraw[];
    uint32_t sbase = (uint32_t)__cvta_generic_to_shared(smraw);

    int tid = threadIdx.x;
    int warp = tid >> 5, lane = tid & 31;
    int wm = warp & 1, wn = warp >> 1;       // 2x4 warps
    int arow = tid >> 2, ach = tid & 3;

    float acc[BM / 32][4][4];
#pragma unroll
    for (int a = 0; a < BM / 32; a++)
#pragma unroll
        for (int b = 0; b < 4; b++)
#pragma unroll
            for (int c = 0; c < 4; c++) acc[a][b][c] = 0.f;

    auto load_stage = [&](int s, int kt) {
        uint32_t st = sbase + s * STAGE;
#pragma unroll
        for (int i = 0; i < BM / 64; i++) {
            int row = arow + 64 * i;
            cp16(st + sw_off(row, ach),
                 A + (size_t)(m0 + row) * KK + kt + ach * 8);
        }
#pragma unroll
        for (int i = 0; i < 2; i++) {
            int id = tid + 256 * i;
            int row = id >> 4, ch = id & 15;
            cp16(st + ABYTES + sw_off256(row, ch),
                 W + (size_t)(kt + row) * N + n0 + ch * 8);
        }
    };

    load_stage(0, 0);
    CP_COMMIT();
    load_stage(1, 32);
    CP_COMMIT();
    load_stage(2, 64);
    CP_COMMIT();

    int r = lane & 7, sub = lane >> 3;
    int b_k_lane = lane & 15;
    int b_ch_lane = lane >> 4;

#pragma unroll 4
    for (int t = 0; t < T; ++t) {
        CP_WAIT2();
        __syncthreads();
        if (t + 3 < T) load_stage((t + 3) & 3, (t + 3) * 32);
        CP_COMMIT();

        uint32_t stb = sbase + (t & 3) * STAGE;
#pragma unroll
        for (int ks = 0; ks < 2; ++ks) {
            uint32_t af[BM / 32][4];
#pragma unroll
            for (int mf = 0; mf < BM / 32; ++mf) {
                int row = wm * (BM / 2) + mf * 16 + (sub & 1) * 8 + r;
                int ch = ks * 2 + (sub >> 1);
                ldsm4(af[mf], stb + sw_off(row, ch));
            }
            uint32_t bw[4][2];
#pragma unroll
            for (int ng = 0; ng < 2; ++ng) {
                int krow = ks * 16 + b_k_lane;
                int ch = wn * 4 + ng * 2 + b_ch_lane;
                uint32_t tmp[4];
                ldsm4t(tmp, stb + ABYTES + sw_off256(krow, ch));
                bw[2 * ng][0] = tmp[0]; bw[2 * ng][1] = tmp[1];
                bw[2 * ng + 1][0] = tmp[2]; bw[2 * ng + 1][1] = tmp[3];
            }
#pragma unroll
            for (int mf = 0; mf < BM / 32; ++mf)
#pragma unroll
                for (int nf = 0; nf < 4; ++nf)
                    mma_f16(acc[mf][nf], af[mf], bw[nf][0], bw[nf][1]);
        }
    }

    int lr = lane >> 2, lc = (lane & 3) * 2;

    if (mode == 0) {
#pragma unroll
        for (int mf = 0; mf < BM / 32; ++mf)
#pragma unroll
            for (int nf = 0; nf < 4; ++nf) {
                int row = m0 + wm * (BM / 2) + mf * 16 + lr;
                int col = n0 + wn * 32 + nf * 8 + lc;
                float b0 = bias[col], b1 = bias[col + 1];
                float2 v0 = make_float2(acc[mf][nf][0] + b0, acc[mf][nf][1] + b1);
                float2 v1 = make_float2(acc[mf][nf][2] + b0, acc[mf][nf][3] + b1);
                *(float2*)&C[(size_t)row * N + col] = v0;
                *(float2*)&C[(size_t)(row + 8) * N + col] = v1;
            }
    } else {
        const float scale = 0.08838834764831845f;  // 1/sqrt(128)
#pragma unroll
        for (int mf = 0; mf < BM / 32; ++mf)
#pragma unroll
            for (int nf = 0; nf < 4; ++nf) {
                int row = m0 + wm * (BM / 2) + mf * 16 + lr;
                int col = n0 + wn * 32 + nf * 8 + lc;
                float b0 = bias[col], b1 = bias[col + 1];
                int hh = col >> 7, d = col & 127;
#pragma unroll
                for (int rr = 0; rr < 2; ++rr) {
                    int r_ = row + rr * 8;
                    float v0 = acc[mf][nf][2 * rr + 0] + b0;
                    float v1 = acc[mf][nf][2 * rr + 1] + b1;
                    if (mode == 1) {
                        int b = r_ >> 8, l = r_ & 255;
                        int j = d >> 1;
                        float e = -((float)(2 * j) / 128.0f) * 9.210340371976184f;
                        float ang = (float)l * expf(e);
                        float sn, cs;
                        sincosf(ang, &sn, &cs);
                        float o1 = (v0 * cs - v1 * sn) * scale;
                        float o2 = (v0 * sn + v1 * cs) * scale;
                        size_t off = ((size_t)(b * H_ + hh) * L_ + l) * HD_ + d;
                        *(uint32_t*)&Oh[off] = packh(o1, o2);
                    } else {
                        int b = r_ >> 11, le = r_ & 2047;
                        size_t off = ((size_t)(b * H_ + hh) * LE_ + le) * HD_ + d;
                        *(uint32_t*)&Oh[off] = packh(v0, v1);
                    }
                }
            }
    }
}

template<int BM, int KK>
__global__ __launch_bounds__(256, 2) void gemm1_kernel(
    const __half* __restrict__ A, const __half* __restrict__ W,
    const float* __restrict__ bias, float* __restrict__ C,
    __half* __restrict__ Oh, int M, int N, int mode)
{
    gemm1_body<BM, KK>(A, W, bias, C, Oh, M, N, mode,
                       blockIdx.y * BM, blockIdx.x * 128);
}

// Q, K, V projections in ONE flattened launch:
// blocks [0,1024) K | [1024,2048) V | [2048,2304) Q
__global__ __launch_bounds__(256, 2) void gemm_qkv_kernel(
    const __half* __restrict__ af, const __half* __restrict__ ef,
    const __half* __restrict__ Wq, const __half* __restrict__ Wk,
    const __half* __restrict__ Wv,
    const float* __restrict__ bq, const float* __restrict__ bk,
    const float* __restrict__ bv,
    __half* __restrict__ Qf, __half* __restrict__ Kf, __half* __restrict__ Vf)
{
    int blk = blockIdx.x;
    if (blk < 1024) {
        gemm1_body<128, DE_>(ef, Wk, bk, nullptr, Kf, B_ * LE_, D_, 2,
                             (blk >> 4) * 128, (blk & 15) * 128);
    } else if (blk < 2048) {
        int b2 = blk - 1024;
        gemm1_body<128, DE_>(ef, Wv, bv, nullptr, Vf, B_ * LE_, D_, 2,
                             (b2 >> 4) * 128, (b2 & 15) * 128);
    } else {
        int b2 = blk - 2048;
        gemm1_body<64, D_>(af, Wq, bq, nullptr, Qf, B_ * L_, D_, 1,
                           (b2 >> 4) * 64, (b2 & 15) * 128);
    }
}

// ---------------- tensor-core flash attention (fp16 x1, split-KV) ------------
__global__ __launch_bounds__(256, 1) void attn_mma_kernel(
    const __half* __restrict__ qf,
    const __half* __restrict__ kf, const __half* __restrict__ vf,
    float* __restrict__ pctx, float* __restrict__ pml)
{
    extern __shared__ uint8_t smraw[];
    uint32_t sb = (uint32_t)__cvta_generic_to_shared(smraw);

    int b = blockIdx.z, h = blockIdx.y;
    int bh = b * H_ + h;
    int split = blockIdx.x & (NSPLIT - 1);
    int q0 = (blockIdx.x / NSPLIT) * 128;
    int kt0 = split * KEYS_PER_SPLIT;
    int tid = threadIdx.x, warp = tid >> 5, lane = tid & 31;
    int r = lane & 7, sub = lane >> 3;
    int row_lo = lane >> 2, kc = (lane & 3) * 2;
    int qrow = q0 + warp * 16;

    const __half* qb = qf + ((size_t)bh * L_ + qrow) * HD_;
    uint32_t aq[8][4];
#pragma unroll
    for (int kff = 0; kff < 8; kff++) {
        int k0 = kff * 16 + kc;
        aq[kff][0] = *(const uint32_t*)(qb + (size_t)row_lo * HD_ + k0);
        aq[kff][1] = *(const uint32_t*)(qb + (size_t)(row_lo + 8) * HD_ + k0);
        aq[kff][2] = *(const uint32_t*)(qb + (size_t)row_lo * HD_ + k0 + 8);
        aq[kff][3] = *(const uint32_t*)(qb + (size_t)(row_lo + 8) * HD_ + k0 + 8);
    }

    float ctx[16][4];
#pragma unroll
    for (int i = 0; i < 16; i++)
#pragma unroll
        for (int j = 0; j < 4; j++) ctx[i][j] = 0.f;
    float m0 = -1e30f, m1 = -1e30f, l0 = 0.f, l1 = 0.f;

    const __half* khb = kf + (size_t)bh * LE_ * HD_;
    const __half* vhb = vf + (size_t)bh * LE_ * HD_;

#define LOAD_TILE(stage, kt) do {                                              \
        uint32_t st_ = sb + (stage) * 32768;                                   \
        _Pragma("unroll")                                                      \
        for (int i_ = 0; i_ < 4; i_++) {                                       \
            int id_ = tid + 256 * i_;                                          \
            int row_ = id_ >> 4, ch_ = id_ & 15;                               \
            uint32_t off_ = row_ * 256 + (((ch_ ^ (row_ & 7))) << 4);          \
            size_t g_ = (size_t)((kt) + row_) * HD_ + ch_ * 8;                 \
            cp16(st_ + off_, khb + g_);                                        \
            cp16(st_ + 16384 + off_, vhb + g_);                                \
        }                                                                      \
    } while (0)

    LOAD_TILE(0, kt0);
    CP_COMMIT();

    int v_le_lane = lane & 15;
    int v_ch_lane = lane >> 4;
    const int NT = KEYS_PER_SPLIT / 64;

    for (int t = 0; t < NT; ++t) {
        CP_WAIT0();
        __syncthreads();
        if (t + 1 < NT) LOAD_TILE((t + 1) & 1, kt0 + (t + 1) * 64);
        CP_COMMIT();

        uint32_t st = sb + (t & 1) * 32768;

        float S[8][4];
#pragma unroll
        for (int i = 0; i < 8; i++)
#pragma unroll
            for (int j = 0; j < 4; j++) S[i][j] = 0.f;

#pragma unroll
        for (int kff = 0; kff < 8; kff++) {
            uint32_t bk[8][2];
#pragma unroll
            for (int ng = 0; ng < 4; ng++) {
                int krow = ng * 16 + (sub >> 1) * 8 + r;
                int ch = kff * 2 + (sub & 1);
                uint32_t ad = st + krow * 256 + ((ch ^ (krow & 7)) << 4);
                uint32_t tmp[4];
                ldsm4(tmp, ad);
                bk[2 * ng][0] = tmp[0]; bk[2 * ng][1] = tmp[1];
                bk[2 * ng + 1][0] = tmp[2]; bk[2 * ng + 1][1] = tmp[3];
            }
#pragma unroll
            for (int nf = 0; nf < 8; nf++)
                mma_f16(S[nf], aq[kff], bk[nf][0], bk[nf][1]);
        }

        float rmax0 = -1e30f, rmax1 = -1e30f;
#pragma unroll
        for (int nf = 0; nf < 8; nf++) {
            rmax0 = fmaxf(rmax0, fmaxf(S[nf][0], S[nf][1]));
            rmax1 = fmaxf(rmax1, fmaxf(S[nf][2], S[nf][3]));
        }
        rmax0 = fmaxf(rmax0, __shfl_xor_sync(0xffffffffu, rmax0, 1));
        rmax0 = fmaxf(rmax0, __shfl_xor_sync(0xffffffffu, rmax0, 2));
        rmax1 = fmaxf(rmax1, __shfl_xor_sync(0xffffffffu, rmax1, 1));
        rmax1 = fmaxf(rmax1, __shfl_xor_sync(0xffffffffu, rmax1, 2));

        float mn0 = fmaxf(m0, rmax0), mn1 = fmaxf(m1, rmax1);
        float corr0 = __expf(m0 - mn0), corr1 = __expf(m1 - mn1);
        m0 = mn0; m1 = mn1;
        l0 *= corr0; l1 *= corr1;
#pragma unroll
        for (int nf = 0; nf < 16; nf++) {
            ctx[nf][0] *= corr0; ctx[nf][1] *= corr0;
            ctx[nf][2] *= corr1; ctx[nf][3] *= corr1;
        }

        uint32_t ap[4][4];
#pragma unroll
        for (int nf = 0; nf < 8; nf++) {
            float p0 = __expf(S[nf][0] - m0);
            float p1 = __expf(S[nf][1] - m0);
            float p2 = __expf(S[nf][2] - m1);
            float p3 = __expf(S[nf][3] - m1);
            l0 += p0 + p1;
            l1 += p2 + p3;
            int kff = nf >> 1;
            int base = (nf & 1) * 2;
            ap[kff][base + 0] = packh(p0, p1);
            ap[kff][base + 1] = packh(p2, p3);
        }

#pragma unroll
        for (int kff = 0; kff < 4; kff++) {
            int le = kff * 16 + v_le_lane;
#pragma unroll
            for (int dg = 0; dg < 8; dg++) {
                int ch = dg * 2 + v_ch_lane;
                uint32_t ad = st + 16384 + le * 256 + ((ch ^ (le & 7)) << 4);
                uint32_t th[4];
                ldsm4t(th, ad);
                mma_f16(ctx[2 * dg],     ap[kff], th[0], th[1]);
                mma_f16(ctx[2 * dg + 1], ap[kff], th[2], th[3]);
            }
        }
    }

    l0 += __shfl_xor_sync(0xffffffffu, l0, 1);
    l0 += __shfl_xor_sync(0xffffffffu, l0, 2);
    l1 += __shfl_xor_sync(0xffffffffu, l1, 1);
    l1 += __shfl_xor_sync(0xffffffffu, l1, 2);

    size_t base = ((size_t)(split * BH_ + bh) * L_ + qrow) * HD_;
#pragma unroll
    for (int nf = 0; nf < 16; nf++) {
        int col = nf * 8 + kc;
        *(float2*)&pctx[base + (size_t)row_lo * HD_ + col] =
            make_float2(ctx[nf][0], ctx[nf][1]);
        *(float2*)&pctx[base + (size_t)(row_lo + 8) * HD_ + col] =
            make_float2(ctx[nf][2], ctx[nf][3]);
    }
    if ((lane & 3) == 0) {
        size_t mb = ((size_t)(split * BH_ + bh) * L_ + qrow) * 2;
        pml[mb + (size_t)row_lo * 2 + 0] = m0;
        pml[mb + (size_t)row_lo * 2 + 1] = l0;
        pml[mb + (size_t)(row_lo + 8) * 2 + 0] = m1;
        pml[mb + (size_t)(row_lo + 8) * 2 + 1] = l1;
    }
}

// ---------------- split-KV merge (8 dims/thread) -----------------------------
__global__ __launch_bounds__(256) void attn_merge_kernel(
    const float* __restrict__ pctx, const float* __restrict__ pml,
    __half* __restrict__ cf)
{
    int idx = blockIdx.x * 256 + threadIdx.x;  // BH*L*HD/8 total
    int d8 = idx & 15;
    int l = (idx >> 4) & (L_ - 1);
    int bh = idx >> 12;

    size_t ml0 = ((size_t)(0 * BH_ + bh) * L_ + l) * 2;
    size_t ml1 = ((size_t)(1 * BH_ + bh) * L_ + l) * 2;
    float m0 = pml[ml0], s0 = pml[ml0 + 1];
    float m1 = pml[ml1], s1 = pml[ml1 + 1];
    float M = fmaxf(m0, m1);
    float w0 = __expf(m0 - M), w1 = __expf(m1 - M);
    float inv = 1.f / (s0 * w0 + s1 * w1);
    float f0 = w0 * inv, f1 = w1 * inv;

    size_t c0 = ((size_t)(0 * BH_ + bh) * L_ + l) * HD_ + 8 * d8;
    size_t c1 = ((size_t)(1 * BH_ + bh) * L_ + l) * HD_ + 8 * d8;
    float4 a0 = *(const float4*)&pctx[c0];
    float4 a1 = *(const float4*)&pctx[c0 + 4];
    float4 b0 = *(const float4*)&pctx[c1];
    float4 b1 = *(const float4*)&pctx[c1 + 4];

    uint4 o;
    o.x = packh(a0.x * f0 + b0.x * f1, a0.y * f0 + b0.y * f1);
    o.y = packh(a0.z * f0 + b0.z * f1, a0.w * f0 + b0.w * f1);
    o.z = packh(a1.x * f0 + b1.x * f1, a1.y * f0 + b1.y * f1);
    o.w = packh(a1.z * f0 + b1.z * f1, a1.w * f0 + b1.w * f1);

    int bb = bh >> 4, hh = bh & 15;
    size_t off = (size_t)(bb * L_ + l) * D_ + hh * HD_ + 8 * d8;
    *(uint4*)&cf[off] = o;
}

// ---------------------------------------------------------------------------
extern "C" void kernel_launch(void* const* d_in, const int* in_sizes, int n_in,
                              void* d_out, int out_size)
{
    const float* x   = (const float*)d_in[0];
    const float* enc = (const float*)d_in[1];
    const float* Wq  = (const float*)d_in[2];
    const float* bq  = (const float*)d_in[3];
    const float* Wk  = (const float*)d_in[4];
    const float* bk  = (const float*)d_in[5];
    const float* Wv  = (const float*)d_in[6];
    const float* bv  = (const float*)d_in[7];
    const float* Wo  = (const float*)d_in[8];
    const float* bo  = (const float*)d_in[9];
    float* out = (float*)d_out;

    __half *af, *ef, *cf, *wq, *wk, *wv, *wo;
    __half *qfp, *kfp, *vfp;
    float *pctx, *pml;
    cudaGetSymbolAddress((void**)&af, g_af);
    cudaGetSymbolAddress((void**)&ef, g_ef);
    cudaGetSymbolAddress((void**)&cf, g_cf);
    cudaGetSymbolAddress((void**)&wq, g_wq);
    cudaGetSymbolAddress((void**)&wk, g_wk);
    cudaGetSymbolAddress((void**)&wv, g_wv);
    cudaGetSymbolAddress((void**)&wo, g_wo);
    cudaGetSymbolAddress((void**)&qfp, g_qf);
    cudaGetSymbolAddress((void**)&kfp, g_kf);
    cudaGetSymbolAddress((void**)&vfp, g_vf);
    cudaGetSymbolAddress((void**)&pctx, g_pctx);
    cudaGetSymbolAddress((void**)&pml, g_pml);

    const int SMEM64  = 4 * (64 * 64 + 8192);     // 49152
    const int SMEM128 = 4 * (128 * 64 + 8192);    // 65536
    cudaFuncSetAttribute((const void*)gemm1_kernel<64, D_>,
                         cudaFuncAttributeMaxDynamicSharedMemorySize, SMEM64);
    cudaFuncSetAttribute((const void*)gemm_qkv_kernel,
                         cudaFuncAttributeMaxDynamicSharedMemorySize, SMEM128);
    cudaFuncSetAttribute((const void*)attn_mma_kernel,
                         cudaFuncAttributeMaxDynamicSharedMemorySize, 65536);

    const int M1 = B_ * L_;    // 1024

    // ---- all fp32->fp16 conversions in ONE launch ----
    round_all_kernel<<<11264, 256>>>(
        (const float4*)x, (uint4*)af, (const float4*)enc, (uint4*)ef,
        (const float4*)Wq, (uint4*)wq, (const float4*)Wk, (uint4*)wk,
        (const float4*)Wv, (uint4*)wv, (const float4*)Wo, (uint4*)wo);

    // ---- Q, K, V projections in ONE launch (2304 CTAs) ----
    gemm_qkv_kernel<<<2304, 256, SMEM128>>>(
        af, ef, wq, wk, wv, bq, bk, bv, qfp, kfp, vfp);

    // ---- flash attention (split-KV x2) -> partials, then merge ----
    attn_mma_kernel<<<dim3((L_ / 128) * NSPLIT, H_, B_), 256, 65536>>>(
        qfp, kfp, vfp, pctx, pml);
    attn_merge_kernel<<<(BH_ * L_ * HD_ / 8) / 256, 256>>>(pctx, pml, cf);

    // ---- out = ctx @ Wo + bo (BM=64, K=2048) ----
    gemm1_kernel<64, D_><<<dim3(D_ / 128, M1 / 64), 256, SMEM64>>>(
        cf, wo, bo, out, nullptr, M1, D_, 0);
}